// round 6
// baseline (speedup 1.0000x reference)
#include <cuda_runtime.h>
#include <cuda_bf16.h>
#include <cstdint>
#include <cstddef>

#define EPSBN 1e-5f
#define N_B   8192
#define IN_F  512
#define H1D   1024
#define H2D   2048

// -------------------- scratch -----------------------------------------------
__device__ __nv_bfloat16 g_xs [3ULL * N_B * IN_F];
__device__ float         g_h1 [(size_t)N_B * 3 * H1D];
__device__ __nv_bfloat16 g_h1s[3ULL * 3 * N_B * H1D];
__device__ float         g_h2 [(size_t)3 * N_B * H2D];
__device__ __nv_bfloat16 g_h2s[3ULL * 3 * N_B * H2D];
__device__ float         g_h3 [(size_t)3 * N_B * H1D];
__device__ __nv_bfloat16 g_h3s[3ULL * 3 * N_B * H1D];
__device__ __nv_bfloat16 g_w1p[3ULL * 3 * H1D * IN_F];
__device__ __nv_bfloat16 g_w2p[3ULL * H2D * H1D];
__device__ __nv_bfloat16 g_w3p[3ULL * H1D * H2D];
__device__ __nv_bfloat16 g_w4p[3ULL * IN_F * H1D];
__device__ float g_c1[3 * H1D];
__device__ float g_c2[H2D];
__device__ float g_c3[H1D];
__device__ float g_c4[IN_F];

// 6-product schedule: A levels hi,hi,mid,hi,mid,lo ; B levels hi,mid,hi,lo,mid,hi
__constant__ int c_aseg[6] = {0, 0, 1, 0, 1, 2};
__constant__ int c_bseg[6] = {0, 1, 0, 2, 1, 0};

// -------------------- helpers ------------------------------------------------
__device__ __forceinline__ uint32_t smem_u32(const void* p) {
    uint32_t a;
    asm("{ .reg .u64 t; cvta.to.shared.u64 t, %1; cvt.u32.u64 %0, t; }" : "=r"(a) : "l"(p));
    return a;
}
__device__ __forceinline__ void split3(float x, __nv_bfloat16& h, __nv_bfloat16& m,
                                       __nv_bfloat16& l) {
    h = __float2bfloat16(x);
    float r = x - __bfloat162float(h);
    m = __float2bfloat16(r);
    l = __float2bfloat16(r - __bfloat162float(m));
}
__device__ __forceinline__ __nv_bfloat162 mk2(__nv_bfloat16 a, __nv_bfloat16 b) {
    __nv_bfloat162 t; t.x = a; t.y = b; return t;
}
__device__ __forceinline__ float bn_scale(float g, float v) {
    float vv = v + EPSBN;
    float a = rsqrtf(vv);
    return g * (a * (1.5f - 0.5f * vv * a * a));
}
__device__ __forceinline__ void lds_x4(uint32_t* r, uint32_t addr) {
    asm volatile("ldmatrix.sync.aligned.m8n8.x4.shared.b16 {%0,%1,%2,%3}, [%4];"
                 : "=r"(r[0]), "=r"(r[1]), "=r"(r[2]), "=r"(r[3]) : "r"(addr));
}
__device__ __forceinline__ void mma16816(float* c, const uint32_t* a, const uint32_t* b) {
    asm volatile(
        "mma.sync.aligned.m16n8k16.row.col.f32.bf16.bf16.f32 "
        "{%0,%1,%2,%3}, {%4,%5,%6,%7}, {%8,%9}, {%0,%1,%2,%3};"
        : "+f"(c[0]), "+f"(c[1]), "+f"(c[2]), "+f"(c[3])
        : "r"(a[0]), "r"(a[1]), "r"(a[2]), "r"(a[3]), "r"(b[0]), "r"(b[1]));
}

// -------------------- weight prep --------------------------------------------
__global__ void prep_w1_split(const float* __restrict__ W, const float* __restrict__ g,
                              const float* __restrict__ be, const float* __restrict__ m,
                              const float* __restrict__ v, __nv_bfloat16* __restrict__ Wp,
                              float* __restrict__ bias) {
    int i = blockIdx.x * blockDim.x + threadIdx.x;
    if (i >= 3 * H1D * IN_F) return;
    int row = i >> 9;
    float a = bn_scale(g[row], v[row]);
    float val = W[i] * a;
    const size_t S = (size_t)3 * H1D * IN_F;
    __nv_bfloat16 h, md, lo;
    split3(val, h, md, lo);
    Wp[i] = h; Wp[i + S] = md; Wp[i + 2 * S] = lo;
    if ((i & (IN_F - 1)) == 0) bias[row] = be[row] - m[row] * a;
}

__global__ void prep_we_split(const float* __restrict__ W, const float* __restrict__ g,
                              const float* __restrict__ be, const float* __restrict__ m,
                              const float* __restrict__ v, __nv_bfloat16* __restrict__ Wp,
                              float* __restrict__ bias, int Cout, int K) {
    int i = blockIdx.x * blockDim.x + threadIdx.x;
    if (i >= Cout * K) return;
    int o = i / K;
    int k = i - o * K;
    float acc = 0.f;
#pragma unroll
    for (int s = 0; s < 3; s++) {
        float a = bn_scale(g[s * Cout + o], v[s * Cout + o]);
        acc += a * W[(size_t)(s * Cout + o) * K + k];
    }
    const size_t S = (size_t)Cout * K;
    __nv_bfloat16 h, md, lo;
    split3(acc, h, md, lo);
    Wp[i] = h; Wp[i + S] = md; Wp[i + 2 * S] = lo;
    if (k == 0) {
        float cb = 0.f;
#pragma unroll
        for (int s = 0; s < 3; s++) {
            float a = bn_scale(g[s * Cout + o], v[s * Cout + o]);
            cb += be[s * Cout + o] - m[s * Cout + o] * a;
        }
        bias[o] = cb;
    }
}

// -------------------- activation split / gate --------------------------------
__global__ void split_x_kernel(const float* __restrict__ x, __nv_bfloat16* __restrict__ o) {
    int i = blockIdx.x * blockDim.x + threadIdx.x;
    if (i >= N_B * IN_F / 2) return;
    float2 v = ((const float2*)x)[i];
    const size_t S = (size_t)N_B * IN_F;
    __nv_bfloat16 h0, m0, l0, h1, m1, l1;
    split3(v.x, h0, m0, l0);
    split3(v.y, h1, m1, l1);
    ((__nv_bfloat162*)o)[i] = mk2(h0, h1);
    ((__nv_bfloat162*)(o + S))[i] = mk2(m0, m1);
    ((__nv_bfloat162*)(o + 2 * S))[i] = mk2(l0, l1);
}

// h1 fp32 [b][s*1024+o]  ->  gated+split [lvl][s][b][o]
__global__ void gate1_split(const float* __restrict__ h1, __nv_bfloat16* __restrict__ out) {
    int i = blockIdx.x * blockDim.x + threadIdx.x;
    if (i >= N_B * 256) return;
    int b = i >> 8;
    int o4 = i & 255;
    const float4* row = (const float4*)(h1 + (size_t)b * 3072);
    float4 v[3] = {row[o4], row[256 + o4], row[512 + o4]};
    float4 mk;
    mk.x = (v[0].x + v[1].x + v[2].x > 0.f) ? 1.f : 0.f;
    mk.y = (v[0].y + v[1].y + v[2].y > 0.f) ? 1.f : 0.f;
    mk.z = (v[0].z + v[1].z + v[2].z > 0.f) ? 1.f : 0.f;
    mk.w = (v[0].w + v[1].w + v[2].w > 0.f) ? 1.f : 0.f;
    const size_t PL = (size_t)3 * N_B * H1D;
#pragma unroll
    for (int s = 0; s < 3; s++) {
        float gv[4] = {v[s].x * mk.x, v[s].y * mk.y, v[s].z * mk.z, v[s].w * mk.w};
        __nv_bfloat16 h[4], md[4], lo[4];
#pragma unroll
        for (int q = 0; q < 4; q++) split3(gv[q], h[q], md[q], lo[q]);
        size_t base = (size_t)s * N_B * H1D + (size_t)b * H1D + (o4 << 2);
        __nv_bfloat162* p0 = (__nv_bfloat162*)(out + base);
        p0[0] = mk2(h[0], h[1]); p0[1] = mk2(h[2], h[3]);
        __nv_bfloat162* p1 = (__nv_bfloat162*)(out + PL + base);
        p1[0] = mk2(md[0], md[1]); p1[1] = mk2(md[2], md[3]);
        __nv_bfloat162* p2 = (__nv_bfloat162*)(out + 2 * PL + base);
        p2[0] = mk2(lo[0], lo[1]); p2[1] = mk2(lo[2], lo[3]);
    }
}

// h fp32 plane-major [s][plane]  ->  gated+split [lvl][s][plane]
__global__ void gate_split(const float* __restrict__ h, __nv_bfloat16* __restrict__ out,
                           size_t plane) {
    size_t i = (size_t)blockIdx.x * blockDim.x + threadIdx.x;
    size_t q4 = plane >> 2;
    if (i >= q4) return;
    const float4* h4 = (const float4*)h;
    float4 v[3] = {h4[i], h4[i + q4], h4[i + 2 * q4]};
    float4 mk;
    mk.x = (v[0].x + v[1].x + v[2].x > 0.f) ? 1.f : 0.f;
    mk.y = (v[0].y + v[1].y + v[2].y > 0.f) ? 1.f : 0.f;
    mk.z = (v[0].z + v[1].z + v[2].z > 0.f) ? 1.f : 0.f;
    mk.w = (v[0].w + v[1].w + v[2].w > 0.f) ? 1.f : 0.f;
    const size_t PL = 3 * plane;
#pragma unroll
    for (int s = 0; s < 3; s++) {
        float gv[4] = {v[s].x * mk.x, v[s].y * mk.y, v[s].z * mk.z, v[s].w * mk.w};
        __nv_bfloat16 h0[4], md[4], lo[4];
#pragma unroll
        for (int q = 0; q < 4; q++) split3(gv[q], h0[q], md[q], lo[q]);
        size_t base = (size_t)s * plane + (i << 2);
        __nv_bfloat162* p0 = (__nv_bfloat162*)(out + base);
        p0[0] = mk2(h0[0], h0[1]); p0[1] = mk2(h0[2], h0[3]);
        __nv_bfloat162* p1 = (__nv_bfloat162*)(out + PL + base);
        p1[0] = mk2(md[0], md[1]); p1[1] = mk2(md[2], md[3]);
        __nv_bfloat162* p2 = (__nv_bfloat162*)(out + 2 * PL + base);
        p2[0] = mk2(lo[0], lo[1]); p2[1] = mk2(lo[2], lo[3]);
    }
}

// -------------------- HMMA GEMM ----------------------------------------------
// C[M,N] = sum_{6 products} A_lvl[M,K] * B_lvl[N,K]^T + bias[N]
// CTA 128x128, BK=64 (128B rows, XOR-8 swizzle), 8 warps (warp tile 64x32),
// mma.sync m16n8k16 bf16->fp32, cp.async 4-stage pipeline.
// Numerics: per-64K-chunk fresh mma accumulator (tacc), drained into the main
// fp32 accumulator with IEEE-RN FADD -> avoids long truncation-biased HMMA
// accumulation chains (cause of the R4 rel_err blowup).
#define STG 4
#define ASZ 16384
#define BSZ 16384
#define SMEM_BYTES (STG * (ASZ + BSZ))

__device__ __forceinline__ void issue_tile(uint32_t abuf, uint32_t bbuf,
                                           const __nv_bfloat16* Ap,
                                           const __nv_bfloat16* Bp, int m0, int n0,
                                           int kk, int KD, int tid) {
#pragma unroll
    for (int j = 0; j < 4; j++) {
        int id = j * 256 + tid;
        int row = id >> 3, c = id & 7;
        uint32_t dst = abuf + (row << 7) + (((c ^ row) & 7) << 4);
        const void* src = (const char*)(Ap + (size_t)(m0 + row) * KD + kk) + (c << 4);
        asm volatile("cp.async.cg.shared.global [%0], [%1], 16;" :: "r"(dst), "l"(src));
    }
#pragma unroll
    for (int j = 0; j < 4; j++) {
        int id = j * 256 + tid;
        int row = id >> 3, c = id & 7;
        uint32_t dst = bbuf + (row << 7) + (((c ^ row) & 7) << 4);
        const void* src = (const char*)(Bp + (size_t)(n0 + row) * KD + kk) + (c << 4);
        asm volatile("cp.async.cg.shared.global [%0], [%1], 16;" :: "r"(dst), "l"(src));
    }
    asm volatile("cp.async.commit_group;" ::: "memory");
}

template <int KDIM, int ILV>
__global__ void __launch_bounds__(256, 1)
gemm_mma(const __nv_bfloat16* __restrict__ A0, const __nv_bfloat16* __restrict__ B0,
         const float* __restrict__ bias, float* __restrict__ C, int M, int N) {
    extern __shared__ __align__(1024) char dsm[];
    const uint32_t Ab = smem_u32(dsm);
    const uint32_t Bb = Ab + STG * ASZ;

    const int tid = threadIdx.x;
    const int wid = tid >> 5;
    const int lane = tid & 31;
    const int warp_m = wid & 1;
    const int warp_n = wid >> 1;
    const int m0 = blockIdx.y * 128;
    const int n0 = blockIdx.x * 128;

    uint32_t aoff[4], boff[2];
#pragma unroll
    for (int mt = 0; mt < 4; mt++)
        aoff[mt] = (uint32_t)(warp_m * 64 + mt * 16 + (lane & 15)) << 7;
#pragma unroll
    for (int np = 0; np < 2; np++)
        boff[np] = (uint32_t)(warp_n * 32 + np * 16 + ((lane >> 4) << 3) + (lane & 7)) << 7;
    const int l7 = lane & 7;
    const int cha = lane >> 4;
    const int chb = (lane >> 3) & 1;

    float acc[4][4][4];
#pragma unroll
    for (int i = 0; i < 4; i++)
#pragma unroll
        for (int j = 0; j < 4; j++)
#pragma unroll
            for (int q = 0; q < 4; q++) acc[i][j][q] = 0.f;

    constexpr int NK = 6 * (KDIM / 64);
    const size_t pas = (size_t)M * KDIM, pbs = (size_t)N * KDIM;

    int ls = 0, lkk = 0;
#pragma unroll
    for (int p = 0; p < STG - 1; p++) {
        issue_tile(Ab + p * ASZ, Bb + p * BSZ, A0 + (size_t)c_aseg[ls] * pas,
                   B0 + (size_t)c_bseg[ls] * pbs, m0, n0, lkk, KDIM, tid);
        lkk += 64;
        if (lkk == KDIM) { lkk = 0; ls++; }
    }

    for (int kt = 0; kt < NK; kt++) {
        const int st = kt & (STG - 1);
        asm volatile("cp.async.wait_group 2;" ::: "memory");
        __syncthreads();

        if (kt + STG - 1 < NK) {
            const int ft = (kt + STG - 1) & (STG - 1);
            issue_tile(Ab + ft * ASZ, Bb + ft * BSZ, A0 + (size_t)c_aseg[ls] * pas,
                       B0 + (size_t)c_bseg[ls] * pbs, m0, n0, lkk, KDIM, tid);
            lkk += 64;
            if (lkk == KDIM) { lkk = 0; ls++; }
        } else {
            asm volatile("cp.async.commit_group;" ::: "memory");
        }

        const uint32_t As_ = Ab + st * ASZ;
        const uint32_t Bs_ = Bb + st * BSZ;

        // fresh short-chain accumulator for this 64-wide K chunk
        float tacc[4][4][4];
#pragma unroll
        for (int i = 0; i < 4; i++)
#pragma unroll
            for (int j = 0; j < 4; j++)
#pragma unroll
                for (int q = 0; q < 4; q++) tacc[i][j][q] = 0.f;

#pragma unroll
        for (int kk = 0; kk < 4; kk++) {
            uint32_t a[4][4], b[2][4];
#pragma unroll
            for (int mt = 0; mt < 4; mt++)
                lds_x4(a[mt], As_ + aoff[mt] + ((((2 * kk + cha) ^ l7) & 7) << 4));
#pragma unroll
            for (int np = 0; np < 2; np++)
                lds_x4(b[np], Bs_ + boff[np] + ((((2 * kk + chb) ^ l7) & 7) << 4));
#pragma unroll
            for (int mt = 0; mt < 4; mt++)
#pragma unroll
                for (int nt = 0; nt < 4; nt++)
                    mma16816(tacc[mt][nt], a[mt], &b[nt >> 1][(nt & 1) * 2]);
        }

        // IEEE-RN drain into main fp32 accumulator
#pragma unroll
        for (int i = 0; i < 4; i++)
#pragma unroll
            for (int j = 0; j < 4; j++)
#pragma unroll
                for (int q = 0; q < 4; q++) acc[i][j][q] += tacc[i][j][q];
    }

    // -------------------- epilogue --------------------
#pragma unroll
    for (int mt = 0; mt < 4; mt++) {
#pragma unroll
        for (int nt = 0; nt < 4; nt++) {
            int r0 = m0 + warp_m * 64 + mt * 16 + (lane >> 2);
            int cc = n0 + warp_n * 32 + nt * 8 + (lane & 3) * 2;
            float b0 = bias[cc], b1 = bias[cc + 1];
            float* ac = acc[mt][nt];
            if (!ILV) {
                float2 v0 = make_float2(ac[0] + b0, ac[1] + b1);
                float2 v1 = make_float2(ac[2] + b0, ac[3] + b1);
                *(float2*)(C + (size_t)r0 * N + cc) = v0;
                *(float2*)(C + (size_t)(r0 + 8) * N + cc) = v1;
            } else {
                int s0 = r0 >> 13, bb0 = r0 & 8191;
                int r1 = r0 + 8;
                int s1 = r1 >> 13, bb1 = r1 & 8191;
                C[(size_t)bb0 * (N * 3) + (size_t)cc * 3 + s0] = ac[0] + b0;
                C[(size_t)bb0 * (N * 3) + (size_t)(cc + 1) * 3 + s0] = ac[1] + b1;
                C[(size_t)bb1 * (N * 3) + (size_t)cc * 3 + s1] = ac[2] + b0;
                C[(size_t)bb1 * (N * 3) + (size_t)(cc + 1) * 3 + s1] = ac[3] + b1;
            }
        }
    }
}

// -------------------- launch --------------------------------------------------
extern "C" void kernel_launch(void* const* d_in, const int* in_sizes, int n_in,
                              void* d_out, int out_size) {
    const float* x  = (const float*)d_in[0];
    const float *W1 = (const float*)d_in[1],  *G1 = (const float*)d_in[2],
                *B1 = (const float*)d_in[3],  *M1 = (const float*)d_in[4],
                *V1 = (const float*)d_in[5];
    const float *W2 = (const float*)d_in[6],  *G2 = (const float*)d_in[7],
                *B2 = (const float*)d_in[8],  *M2 = (const float*)d_in[9],
                *V2 = (const float*)d_in[10];
    const float *W3 = (const float*)d_in[11], *G3 = (const float*)d_in[12],
                *B3 = (const float*)d_in[13], *M3 = (const float*)d_in[14],
                *V3 = (const float*)d_in[15];
    const float *W4 = (const float*)d_in[16], *G4 = (const float*)d_in[17],
                *B4 = (const float*)d_in[18], *M4 = (const float*)d_in[19],
                *V4 = (const float*)d_in[20];
    float* out = (float*)d_out;

    __nv_bfloat16 *xs, *h1s, *h2s, *h3s, *w1p, *w2p, *w3p, *w4p;
    float *h1, *h2, *h3, *c1, *c2, *c3, *c4;
    cudaGetSymbolAddress((void**)&xs, g_xs);
    cudaGetSymbolAddress((void**)&h1, g_h1);
    cudaGetSymbolAddress((void**)&h1s, g_h1s);
    cudaGetSymbolAddress((void**)&h2, g_h2);
    cudaGetSymbolAddress((void**)&h2s, g_h2s);
    cudaGetSymbolAddress((void**)&h3, g_h3);
    cudaGetSymbolAddress((void**)&h3s, g_h3s);
    cudaGetSymbolAddress((void**)&w1p, g_w1p);
    cudaGetSymbolAddress((void**)&w2p, g_w2p);
    cudaGetSymbolAddress((void**)&w3p, g_w3p);
    cudaGetSymbolAddress((void**)&w4p, g_w4p);
    cudaGetSymbolAddress((void**)&c1, g_c1);
    cudaGetSymbolAddress((void**)&c2, g_c2);
    cudaGetSymbolAddress((void**)&c3, g_c3);
    cudaGetSymbolAddress((void**)&c4, g_c4);

    cudaFuncSetAttribute(gemm_mma<512, 0>,  cudaFuncAttributeMaxDynamicSharedMemorySize, SMEM_BYTES);
    cudaFuncSetAttribute(gemm_mma<1024, 0>, cudaFuncAttributeMaxDynamicSharedMemorySize, SMEM_BYTES);
    cudaFuncSetAttribute(gemm_mma<2048, 0>, cudaFuncAttributeMaxDynamicSharedMemorySize, SMEM_BYTES);
    cudaFuncSetAttribute(gemm_mma<1024, 1>, cudaFuncAttributeMaxDynamicSharedMemorySize, SMEM_BYTES);

    const int T = 256;
    split_x_kernel<<<(N_B * IN_F / 2 + T - 1) / T, T>>>(x, xs);
    prep_w1_split<<<(3 * H1D * IN_F + T - 1) / T, T>>>(W1, G1, B1, M1, V1, w1p, c1);
    prep_we_split<<<(H2D * H1D + T - 1) / T, T>>>(W2, G2, B2, M2, V2, w2p, c2, H2D, H1D);
    prep_we_split<<<(H1D * H2D + T - 1) / T, T>>>(W3, G3, B3, M3, V3, w3p, c3, H1D, H2D);
    prep_we_split<<<(IN_F * H1D + T - 1) / T, T>>>(W4, G4, B4, M4, V4, w4p, c4, IN_F, H1D);

    // L1: [8192,512] x [3072,512]^T -> h1 [8192,3072]
    gemm_mma<512, 0><<<dim3(3 * H1D / 128, N_B / 128), T, SMEM_BYTES>>>(xs, w1p, c1, h1, N_B, 3 * H1D);
    gate1_split<<<(N_B * 256 + T - 1) / T, T>>>(h1, h1s);
    // L2: [24576,1024] x [2048,1024]^T
    gemm_mma<1024, 0><<<dim3(H2D / 128, 3 * N_B / 128), T, SMEM_BYTES>>>(h1s, w2p, c2, h2, 3 * N_B, H2D);
    gate_split<<<(N_B * H2D / 4 + T - 1) / T, T>>>(h2, h2s, (size_t)N_B * H2D);
    // L3: [24576,2048] x [1024,2048]^T
    gemm_mma<2048, 0><<<dim3(H1D / 128, 3 * N_B / 128), T, SMEM_BYTES>>>(h2s, w3p, c3, h3, 3 * N_B, H1D);
    gate_split<<<(N_B * H1D / 4 + T - 1) / T, T>>>(h3, h3s, (size_t)N_B * H1D);
    // L4: [24576,1024] x [512,1024]^T -> interleaved out [b][o][s]
    gemm_mma<1024, 1><<<dim3(IN_F / 128, 3 * N_B / 128), T, SMEM_BYTES>>>(h3s, w4p, c4, out, 3 * N_B, IN_F);
}

// round 7
// speedup vs baseline: 1.3461x; 1.3461x over previous
#include <cuda_runtime.h>
#include <cuda_bf16.h>
#include <cstdint>
#include <cstddef>

#define EPSBN 1e-5f
#define N_B   8192
#define IN_F  512
#define H1D   1024
#define H2D   2048

// -------------------- scratch -----------------------------------------------
__device__ __nv_bfloat16 g_xs [3ULL * N_B * IN_F];
__device__ float         g_h1 [(size_t)N_B * 3 * H1D];
__device__ __nv_bfloat16 g_h1s[3ULL * 3 * N_B * H1D];
__device__ float         g_h2 [(size_t)3 * N_B * H2D];
__device__ __nv_bfloat16 g_h2s[3ULL * 3 * N_B * H2D];
__device__ float         g_h3 [(size_t)3 * N_B * H1D];
__device__ __nv_bfloat16 g_h3s[3ULL * 3 * N_B * H1D];
__device__ __nv_bfloat16 g_w1p[3ULL * 3 * H1D * IN_F];
__device__ __nv_bfloat16 g_w2p[3ULL * H2D * H1D];
__device__ __nv_bfloat16 g_w3p[3ULL * H1D * H2D];
__device__ __nv_bfloat16 g_w4p[3ULL * IN_F * H1D];
__device__ float g_c1[3 * H1D];
__device__ float g_c2[H2D];
__device__ float g_c3[H1D];
__device__ float g_c4[IN_F];

// -------------------- helpers ------------------------------------------------
__device__ __forceinline__ uint32_t smem_u32(const void* p) {
    uint32_t a;
    asm("{ .reg .u64 t; cvta.to.shared.u64 t, %1; cvt.u32.u64 %0, t; }" : "=r"(a) : "l"(p));
    return a;
}
__device__ __forceinline__ void split3(float x, __nv_bfloat16& h, __nv_bfloat16& m,
                                       __nv_bfloat16& l) {
    h = __float2bfloat16(x);
    float r = x - __bfloat162float(h);
    m = __float2bfloat16(r);
    l = __float2bfloat16(r - __bfloat162float(m));
}
__device__ __forceinline__ __nv_bfloat162 mk2(__nv_bfloat16 a, __nv_bfloat16 b) {
    __nv_bfloat162 t; t.x = a; t.y = b; return t;
}
__device__ __forceinline__ float bn_scale(float g, float v) {
    float vv = v + EPSBN;
    float a = rsqrtf(vv);
    return g * (a * (1.5f - 0.5f * vv * a * a));
}
__device__ __forceinline__ void lds_x4(uint32_t* r, uint32_t addr) {
    asm volatile("ldmatrix.sync.aligned.m8n8.x4.shared.b16 {%0,%1,%2,%3}, [%4];"
                 : "=r"(r[0]), "=r"(r[1]), "=r"(r[2]), "=r"(r[3]) : "r"(addr));
}
__device__ __forceinline__ void mma16816(float* c, const uint32_t* a, const uint32_t* b) {
    asm volatile(
        "mma.sync.aligned.m16n8k16.row.col.f32.bf16.bf16.f32 "
        "{%0,%1,%2,%3}, {%4,%5,%6,%7}, {%8,%9}, {%0,%1,%2,%3};"
        : "+f"(c[0]), "+f"(c[1]), "+f"(c[2]), "+f"(c[3])
        : "r"(a[0]), "r"(a[1]), "r"(a[2]), "r"(a[3]), "r"(b[0]), "r"(b[1]));
}
// first mma of a chain: writes d = a*b + 0 (no tacc pre-zeroing needed)
__device__ __forceinline__ void mma16816_z(float* c, const uint32_t* a, const uint32_t* b) {
    asm volatile(
        "mma.sync.aligned.m16n8k16.row.col.f32.bf16.bf16.f32 "
        "{%0,%1,%2,%3}, {%4,%5,%6,%7}, {%8,%9}, {%10,%10,%10,%10};"
        : "=f"(c[0]), "=f"(c[1]), "=f"(c[2]), "=f"(c[3])
        : "r"(a[0]), "r"(a[1]), "r"(a[2]), "r"(a[3]), "r"(b[0]), "r"(b[1]), "f"(0.f));
}

// -------------------- weight prep --------------------------------------------
__global__ void prep_w1_split(const float* __restrict__ W, const float* __restrict__ g,
                              const float* __restrict__ be, const float* __restrict__ m,
                              const float* __restrict__ v, __nv_bfloat16* __restrict__ Wp,
                              float* __restrict__ bias) {
    int i = blockIdx.x * blockDim.x + threadIdx.x;
    if (i >= 3 * H1D * IN_F) return;
    int row = i >> 9;
    float a = bn_scale(g[row], v[row]);
    float val = W[i] * a;
    const size_t S = (size_t)3 * H1D * IN_F;
    __nv_bfloat16 h, md, lo;
    split3(val, h, md, lo);
    Wp[i] = h; Wp[i + S] = md; Wp[i + 2 * S] = lo;
    if ((i & (IN_F - 1)) == 0) bias[row] = be[row] - m[row] * a;
}

__global__ void prep_we_split(const float* __restrict__ W, const float* __restrict__ g,
                              const float* __restrict__ be, const float* __restrict__ m,
                              const float* __restrict__ v, __nv_bfloat16* __restrict__ Wp,
                              float* __restrict__ bias, int Cout, int K) {
    int i = blockIdx.x * blockDim.x + threadIdx.x;
    if (i >= Cout * K) return;
    int o = i / K;
    int k = i - o * K;
    float acc = 0.f;
#pragma unroll
    for (int s = 0; s < 3; s++) {
        float a = bn_scale(g[s * Cout + o], v[s * Cout + o]);
        acc += a * W[(size_t)(s * Cout + o) * K + k];
    }
    const size_t S = (size_t)Cout * K;
    __nv_bfloat16 h, md, lo;
    split3(acc, h, md, lo);
    Wp[i] = h; Wp[i + S] = md; Wp[i + 2 * S] = lo;
    if (k == 0) {
        float cb = 0.f;
#pragma unroll
        for (int s = 0; s < 3; s++) {
            float a = bn_scale(g[s * Cout + o], v[s * Cout + o]);
            cb += be[s * Cout + o] - m[s * Cout + o] * a;
        }
        bias[o] = cb;
    }
}

// -------------------- activation split / gate --------------------------------
__global__ void split_x_kernel(const float* __restrict__ x, __nv_bfloat16* __restrict__ o) {
    int i = blockIdx.x * blockDim.x + threadIdx.x;
    if (i >= N_B * IN_F / 2) return;
    float2 v = ((const float2*)x)[i];
    const size_t S = (size_t)N_B * IN_F;
    __nv_bfloat16 h0, m0, l0, h1, m1, l1;
    split3(v.x, h0, m0, l0);
    split3(v.y, h1, m1, l1);
    ((__nv_bfloat162*)o)[i] = mk2(h0, h1);
    ((__nv_bfloat162*)(o + S))[i] = mk2(m0, m1);
    ((__nv_bfloat162*)(o + 2 * S))[i] = mk2(l0, l1);
}

// h1 fp32 [b][s*1024+o]  ->  gated+split [lvl][s][b][o]
__global__ void gate1_split(const float* __restrict__ h1, __nv_bfloat16* __restrict__ out) {
    int i = blockIdx.x * blockDim.x + threadIdx.x;
    if (i >= N_B * 256) return;
    int b = i >> 8;
    int o4 = i & 255;
    const float4* row = (const float4*)(h1 + (size_t)b * 3072);
    float4 v[3] = {row[o4], row[256 + o4], row[512 + o4]};
    float4 mk;
    mk.x = (v[0].x + v[1].x + v[2].x > 0.f) ? 1.f : 0.f;
    mk.y = (v[0].y + v[1].y + v[2].y > 0.f) ? 1.f : 0.f;
    mk.z = (v[0].z + v[1].z + v[2].z > 0.f) ? 1.f : 0.f;
    mk.w = (v[0].w + v[1].w + v[2].w > 0.f) ? 1.f : 0.f;
    const size_t PL = (size_t)3 * N_B * H1D;
#pragma unroll
    for (int s = 0; s < 3; s++) {
        float gv[4] = {v[s].x * mk.x, v[s].y * mk.y, v[s].z * mk.z, v[s].w * mk.w};
        __nv_bfloat16 h[4], md[4], lo[4];
#pragma unroll
        for (int q = 0; q < 4; q++) split3(gv[q], h[q], md[q], lo[q]);
        size_t base = (size_t)s * N_B * H1D + (size_t)b * H1D + (o4 << 2);
        __nv_bfloat162* p0 = (__nv_bfloat162*)(out + base);
        p0[0] = mk2(h[0], h[1]); p0[1] = mk2(h[2], h[3]);
        __nv_bfloat162* p1 = (__nv_bfloat162*)(out + PL + base);
        p1[0] = mk2(md[0], md[1]); p1[1] = mk2(md[2], md[3]);
        __nv_bfloat162* p2 = (__nv_bfloat162*)(out + 2 * PL + base);
        p2[0] = mk2(lo[0], lo[1]); p2[1] = mk2(lo[2], lo[3]);
    }
}

// h fp32 plane-major [s][plane]  ->  gated+split [lvl][s][plane]
__global__ void gate_split(const float* __restrict__ h, __nv_bfloat16* __restrict__ out,
                           size_t plane) {
    size_t i = (size_t)blockIdx.x * blockDim.x + threadIdx.x;
    size_t q4 = plane >> 2;
    if (i >= q4) return;
    const float4* h4 = (const float4*)h;
    float4 v[3] = {h4[i], h4[i + q4], h4[i + 2 * q4]};
    float4 mk;
    mk.x = (v[0].x + v[1].x + v[2].x > 0.f) ? 1.f : 0.f;
    mk.y = (v[0].y + v[1].y + v[2].y > 0.f) ? 1.f : 0.f;
    mk.z = (v[0].z + v[1].z + v[2].z > 0.f) ? 1.f : 0.f;
    mk.w = (v[0].w + v[1].w + v[2].w > 0.f) ? 1.f : 0.f;
    const size_t PL = 3 * plane;
#pragma unroll
    for (int s = 0; s < 3; s++) {
        float gv[4] = {v[s].x * mk.x, v[s].y * mk.y, v[s].z * mk.z, v[s].w * mk.w};
        __nv_bfloat16 h0[4], md[4], lo[4];
#pragma unroll
        for (int q = 0; q < 4; q++) split3(gv[q], h0[q], md[q], lo[q]);
        size_t base = (size_t)s * plane + (i << 2);
        __nv_bfloat162* p0 = (__nv_bfloat162*)(out + base);
        p0[0] = mk2(h0[0], h0[1]); p0[1] = mk2(h0[2], h0[3]);
        __nv_bfloat162* p1 = (__nv_bfloat162*)(out + PL + base);
        p1[0] = mk2(md[0], md[1]); p1[1] = mk2(md[2], md[3]);
        __nv_bfloat162* p2 = (__nv_bfloat162*)(out + 2 * PL + base);
        p2[0] = mk2(lo[0], lo[1]); p2[1] = mk2(lo[2], lo[3]);
    }
}

// -------------------- fused 6-product HMMA GEMM ------------------------------
// C[M,N] = sum over {hh,hm,hl,mh,mm,lh} A_i[M,K] * B_j[N,K]^T + bias[N]
// One K sweep. Each 64-wide K super-stage loads 6 tiles (A hi/mid/lo,
// B hi/mid/lo, 16KB each = 96KB) and runs all 6 products against them,
// reusing A fragments across B levels. Double-buffered (192KB smem).
// tacc chain = 2 kk x 6 products (12 mma), RN-drained into fp32 acc.
#define TSZ 16384
#define SUPER (6 * TSZ)
#define SMEM_BYTES (2 * SUPER)

__device__ __forceinline__ void load_tile16(uint32_t dst, const __nv_bfloat16* src,
                                            int row0, int KD, int k0, int tid) {
#pragma unroll
    for (int j = 0; j < 4; j++) {
        int id = j * 256 + tid;
        int row = id >> 3, c = id & 7;
        uint32_t d = dst + (row << 7) + (((c ^ row) & 7) << 4);
        const void* s = (const char*)(src + (size_t)(row0 + row) * KD + k0) + (c << 4);
        asm volatile("cp.async.cg.shared.global [%0], [%1], 16;" :: "r"(d), "l"(s));
    }
}

template <int KDIM, int ILV>
__global__ void __launch_bounds__(256, 1)
gemm_fused(const __nv_bfloat16* __restrict__ A0, const __nv_bfloat16* __restrict__ B0,
           const float* __restrict__ bias, float* __restrict__ C, int M, int N) {
    extern __shared__ __align__(1024) char dsm[];
    const uint32_t Sb = smem_u32(dsm);

    const int tid = threadIdx.x;
    const int wid = tid >> 5;
    const int lane = tid & 31;
    const int warp_m = wid & 1;
    const int warp_n = wid >> 1;
    const int m0 = blockIdx.y * 128;
    const int n0 = blockIdx.x * 128;

    uint32_t aoff[4], boff[2];
#pragma unroll
    for (int mt = 0; mt < 4; mt++)
        aoff[mt] = (uint32_t)(warp_m * 64 + mt * 16 + (lane & 15)) << 7;
#pragma unroll
    for (int np = 0; np < 2; np++)
        boff[np] = (uint32_t)(warp_n * 32 + np * 16 + ((lane >> 4) << 3) + (lane & 7)) << 7;
    const int l7 = lane & 7;
    const int cha = lane >> 4;
    const int chb = (lane >> 3) & 1;

    float acc[4][4][4];
#pragma unroll
    for (int i = 0; i < 4; i++)
#pragma unroll
        for (int j = 0; j < 4; j++)
#pragma unroll
            for (int q = 0; q < 4; q++) acc[i][j][q] = 0.f;

    constexpr int NSUP = KDIM / 64;
    const size_t pas = (size_t)M * KDIM, pbs = (size_t)N * KDIM;

    // prologue: load super-stage 0 into buffer 0
    {
        uint32_t buf = Sb;
#pragma unroll
        for (int lvl = 0; lvl < 3; lvl++) {
            load_tile16(buf + lvl * TSZ, A0 + (size_t)lvl * pas, m0, KDIM, 0, tid);
            load_tile16(buf + (3 + lvl) * TSZ, B0 + (size_t)lvl * pbs, n0, KDIM, 0, tid);
        }
        asm volatile("cp.async.commit_group;" ::: "memory");
    }

    for (int t = 0; t < NSUP; t++) {
        asm volatile("cp.async.wait_group 0;" ::: "memory");
        __syncthreads();

        if (t + 1 < NSUP) {
            uint32_t buf = Sb + ((t + 1) & 1) * SUPER;
            int k0 = (t + 1) * 64;
#pragma unroll
            for (int lvl = 0; lvl < 3; lvl++) {
                load_tile16(buf + lvl * TSZ, A0 + (size_t)lvl * pas, m0, KDIM, k0, tid);
                load_tile16(buf + (3 + lvl) * TSZ, B0 + (size_t)lvl * pbs, n0, KDIM, k0, tid);
            }
            asm volatile("cp.async.commit_group;" ::: "memory");
        }

        const uint32_t Ab = Sb + (t & 1) * SUPER;
        const uint32_t Bb = Ab + 3 * TSZ;

#pragma unroll
        for (int half = 0; half < 2; half++) {
            float tacc[4][4][4];   // zero-written by first mma (mma16816_z)
#pragma unroll
            for (int kk2 = 0; kk2 < 2; kk2++) {
                const int kk = half * 2 + kk2;
                const uint32_t swa = (uint32_t)(((2 * kk + cha) ^ l7) & 7) << 4;
                const uint32_t swb = (uint32_t)(((2 * kk + chb) ^ l7) & 7) << 4;

                uint32_t b[3][2][4];
#pragma unroll
                for (int lvl = 0; lvl < 3; lvl++)
#pragma unroll
                    for (int np = 0; np < 2; np++)
                        lds_x4(b[lvl][np], Bb + lvl * TSZ + boff[np] + swb);

                uint32_t a[4][4];
                // ---- A hi: products hh, hm, hl ----
#pragma unroll
                for (int mt = 0; mt < 4; mt++) lds_x4(a[mt], Ab + 0 * TSZ + aoff[mt] + swa);
                if (kk2 == 0) {
#pragma unroll
                    for (int mt = 0; mt < 4; mt++)
#pragma unroll
                        for (int nt = 0; nt < 4; nt++)
                            mma16816_z(tacc[mt][nt], a[mt], &b[0][nt >> 1][(nt & 1) * 2]);
                } else {
#pragma unroll
                    for (int mt = 0; mt < 4; mt++)
#pragma unroll
                        for (int nt = 0; nt < 4; nt++)
                            mma16816(tacc[mt][nt], a[mt], &b[0][nt >> 1][(nt & 1) * 2]);
                }
#pragma unroll
                for (int mt = 0; mt < 4; mt++)
#pragma unroll
                    for (int nt = 0; nt < 4; nt++)
                        mma16816(tacc[mt][nt], a[mt], &b[1][nt >> 1][(nt & 1) * 2]);
#pragma unroll
                for (int mt = 0; mt < 4; mt++)
#pragma unroll
                    for (int nt = 0; nt < 4; nt++)
                        mma16816(tacc[mt][nt], a[mt], &b[2][nt >> 1][(nt & 1) * 2]);
                // ---- A mid: products mh, mm ----
#pragma unroll
                for (int mt = 0; mt < 4; mt++) lds_x4(a[mt], Ab + 1 * TSZ + aoff[mt] + swa);
#pragma unroll
                for (int mt = 0; mt < 4; mt++)
#pragma unroll
                    for (int nt = 0; nt < 4; nt++)
                        mma16816(tacc[mt][nt], a[mt], &b[0][nt >> 1][(nt & 1) * 2]);
#pragma unroll
                for (int mt = 0; mt < 4; mt++)
#pragma unroll
                    for (int nt = 0; nt < 4; nt++)
                        mma16816(tacc[mt][nt], a[mt], &b[1][nt >> 1][(nt & 1) * 2]);
                // ---- A lo: product lh ----
#pragma unroll
                for (int mt = 0; mt < 4; mt++) lds_x4(a[mt], Ab + 2 * TSZ + aoff[mt] + swa);
#pragma unroll
                for (int mt = 0; mt < 4; mt++)
#pragma unroll
                    for (int nt = 0; nt < 4; nt++)
                        mma16816(tacc[mt][nt], a[mt], &b[0][nt >> 1][(nt & 1) * 2]);
            }
            // RN drain
#pragma unroll
            for (int i = 0; i < 4; i++)
#pragma unroll
                for (int j = 0; j < 4; j++)
#pragma unroll
                    for (int q = 0; q < 4; q++) acc[i][j][q] += tacc[i][j][q];
        }
    }

    // -------------------- epilogue --------------------
#pragma unroll
    for (int mt = 0; mt < 4; mt++) {
#pragma unroll
        for (int nt = 0; nt < 4; nt++) {
            int r0 = m0 + warp_m * 64 + mt * 16 + (lane >> 2);
            int cc = n0 + warp_n * 32 + nt * 8 + (lane & 3) * 2;
            float b0 = bias[cc], b1 = bias[cc + 1];
            float* ac = acc[mt][nt];
            if (!ILV) {
                float2 v0 = make_float2(ac[0] + b0, ac[1] + b1);
                float2 v1 = make_float2(ac[2] + b0, ac[3] + b1);
                *(float2*)(C + (size_t)r0 * N + cc) = v0;
                *(float2*)(C + (size_t)(r0 + 8) * N + cc) = v1;
            } else {
                int s0 = r0 >> 13, bb0 = r0 & 8191;
                int r1 = r0 + 8;
                int s1 = r1 >> 13, bb1 = r1 & 8191;
                C[(size_t)bb0 * (N * 3) + (size_t)cc * 3 + s0] = ac[0] + b0;
                C[(size_t)bb0 * (N * 3) + (size_t)(cc + 1) * 3 + s0] = ac[1] + b1;
                C[(size_t)bb1 * (N * 3) + (size_t)cc * 3 + s1] = ac[2] + b0;
                C[(size_t)bb1 * (N * 3) + (size_t)(cc + 1) * 3 + s1] = ac[3] + b1;
            }
        }
    }
}

// -------------------- launch --------------------------------------------------
extern "C" void kernel_launch(void* const* d_in, const int* in_sizes, int n_in,
                              void* d_out, int out_size) {
    const float* x  = (const float*)d_in[0];
    const float *W1 = (const float*)d_in[1],  *G1 = (const float*)d_in[2],
                *B1 = (const float*)d_in[3],  *M1 = (const float*)d_in[4],
                *V1 = (const float*)d_in[5];
    const float *W2 = (const float*)d_in[6],  *G2 = (const float*)d_in[7],
                *B2 = (const float*)d_in[8],  *M2 = (const float*)d_in[9],
                *V2 = (const float*)d_in[10];
    const float *W3 = (const float*)d_in[11], *G3 = (const float*)d_in[12],
                *B3 = (const float*)d_in[13], *M3 = (const float*)d_in[14],
                *V3 = (const float*)d_in[15];
    const float *W4 = (const float*)d_in[16], *G4 = (const float*)d_in[17],
                *B4 = (const float*)d_in[18], *M4 = (const float*)d_in[19],
                *V4 = (const float*)d_in[20];
    float* out = (float*)d_out;

    __nv_bfloat16 *xs, *h1s, *h2s, *h3s, *w1p, *w2p, *w3p, *w4p;
    float *h1, *h2, *h3, *c1, *c2, *c3, *c4;
    cudaGetSymbolAddress((void**)&xs, g_xs);
    cudaGetSymbolAddress((void**)&h1, g_h1);
    cudaGetSymbolAddress((void**)&h1s, g_h1s);
    cudaGetSymbolAddress((void**)&h2, g_h2);
    cudaGetSymbolAddress((void**)&h2s, g_h2s);
    cudaGetSymbolAddress((void**)&h3, g_h3);
    cudaGetSymbolAddress((void**)&h3s, g_h3s);
    cudaGetSymbolAddress((void**)&w1p, g_w1p);
    cudaGetSymbolAddress((void**)&w2p, g_w2p);
    cudaGetSymbolAddress((void**)&w3p, g_w3p);
    cudaGetSymbolAddress((void**)&w4p, g_w4p);
    cudaGetSymbolAddress((void**)&c1, g_c1);
    cudaGetSymbolAddress((void**)&c2, g_c2);
    cudaGetSymbolAddress((void**)&c3, g_c3);
    cudaGetSymbolAddress((void**)&c4, g_c4);

    cudaFuncSetAttribute(gemm_fused<512, 0>,  cudaFuncAttributeMaxDynamicSharedMemorySize, SMEM_BYTES);
    cudaFuncSetAttribute(gemm_fused<1024, 0>, cudaFuncAttributeMaxDynamicSharedMemorySize, SMEM_BYTES);
    cudaFuncSetAttribute(gemm_fused<2048, 0>, cudaFuncAttributeMaxDynamicSharedMemorySize, SMEM_BYTES);
    cudaFuncSetAttribute(gemm_fused<1024, 1>, cudaFuncAttributeMaxDynamicSharedMemorySize, SMEM_BYTES);

    const int T = 256;
    split_x_kernel<<<(N_B * IN_F / 2 + T - 1) / T, T>>>(x, xs);
    prep_w1_split<<<(3 * H1D * IN_F + T - 1) / T, T>>>(W1, G1, B1, M1, V1, w1p, c1);
    prep_we_split<<<(H2D * H1D + T - 1) / T, T>>>(W2, G2, B2, M2, V2, w2p, c2, H2D, H1D);
    prep_we_split<<<(H1D * H2D + T - 1) / T, T>>>(W3, G3, B3, M3, V3, w3p, c3, H1D, H2D);
    prep_we_split<<<(IN_F * H1D + T - 1) / T, T>>>(W4, G4, B4, M4, V4, w4p, c4, IN_F, H1D);

    // L1: [8192,512] x [3072,512]^T -> h1 [8192,3072]
    gemm_fused<512, 0><<<dim3(3 * H1D / 128, N_B / 128), T, SMEM_BYTES>>>(xs, w1p, c1, h1, N_B, 3 * H1D);
    gate1_split<<<(N_B * 256 + T - 1) / T, T>>>(h1, h1s);
    // L2: [24576,1024] x [2048,1024]^T
    gemm_fused<1024, 0><<<dim3(H2D / 128, 3 * N_B / 128), T, SMEM_BYTES>>>(h1s, w2p, c2, h2, 3 * N_B, H2D);
    gate_split<<<(N_B * H2D / 4 + T - 1) / T, T>>>(h2, h2s, (size_t)N_B * H2D);
    // L3: [24576,2048] x [1024,2048]^T
    gemm_fused<2048, 0><<<dim3(H1D / 128, 3 * N_B / 128), T, SMEM_BYTES>>>(h2s, w3p, c3, h3, 3 * N_B, H1D);
    gate_split<<<(N_B * H1D / 4 + T - 1) / T, T>>>(h3, h3s, (size_t)N_B * H1D);
    // L4: [24576,1024] x [512,1024]^T -> interleaved out [b][o][s]
    gemm_fused<1024, 1><<<dim3(IN_F / 128, 3 * N_B / 128), T, SMEM_BYTES>>>(h3s, w4p, c4, out, 3 * N_B, IN_F);
}

// round 8
// speedup vs baseline: 1.9034x; 1.4140x over previous
#include <cuda_runtime.h>
#include <cuda_fp16.h>
#include <cstdint>
#include <cstddef>

#define EPSBN 1e-5f
#define N_B   8192
#define IN_F  512
#define H1D   1024
#define H2D   2048

// -------------------- scratch -----------------------------------------------
__device__ __half g_xs [2ULL * N_B * IN_F];
__device__ float  g_h1 [(size_t)N_B * 3 * H1D];
__device__ __half g_h1s[2ULL * 3 * N_B * H1D];
__device__ float  g_h2 [(size_t)3 * N_B * H2D];
__device__ __half g_h2s[2ULL * 3 * N_B * H2D];
__device__ float  g_h3 [(size_t)3 * N_B * H1D];
__device__ __half g_h3s[2ULL * 3 * N_B * H1D];
__device__ __half g_w1p[2ULL * 3 * H1D * IN_F];
__device__ __half g_w2p[2ULL * H2D * H1D];
__device__ __half g_w3p[2ULL * H1D * H2D];
__device__ __half g_w4p[2ULL * IN_F * H1D];
__device__ float g_c1[3 * H1D];
__device__ float g_c2[H2D];
__device__ float g_c3[H1D];
__device__ float g_c4[IN_F];

// -------------------- helpers ------------------------------------------------
__device__ __forceinline__ uint32_t smem_u32(const void* p) {
    uint32_t a;
    asm("{ .reg .u64 t; cvta.to.shared.u64 t, %1; cvt.u32.u64 %0, t; }" : "=r"(a) : "l"(p));
    return a;
}
__device__ __forceinline__ void split2(float x, __half& h, __half& l) {
    h = __float2half_rn(x);
    l = __float2half_rn(x - __half2float(h));
}
__device__ __forceinline__ __half2 mkh2(__half a, __half b) {
    __half2 t; t.x = a; t.y = b; return t;
}
__device__ __forceinline__ float bn_scale(float g, float v) {
    float vv = v + EPSBN;
    float a = rsqrtf(vv);
    return g * (a * (1.5f - 0.5f * vv * a * a));
}
__device__ __forceinline__ void lds_x4(uint32_t* r, uint32_t addr) {
    asm volatile("ldmatrix.sync.aligned.m8n8.x4.shared.b16 {%0,%1,%2,%3}, [%4];"
                 : "=r"(r[0]), "=r"(r[1]), "=r"(r[2]), "=r"(r[3]) : "r"(addr));
}
__device__ __forceinline__ void mma16816(float* c, const uint32_t* a, const uint32_t* b) {
    asm volatile(
        "mma.sync.aligned.m16n8k16.row.col.f32.f16.f16.f32 "
        "{%0,%1,%2,%3}, {%4,%5,%6,%7}, {%8,%9}, {%0,%1,%2,%3};"
        : "+f"(c[0]), "+f"(c[1]), "+f"(c[2]), "+f"(c[3])
        : "r"(a[0]), "r"(a[1]), "r"(a[2]), "r"(a[3]), "r"(b[0]), "r"(b[1]));
}
// first mma of a chain: d = a*b + 0 (avoids tacc pre-zeroing)
__device__ __forceinline__ void mma16816_z(float* c, const uint32_t* a, const uint32_t* b) {
    asm volatile(
        "mma.sync.aligned.m16n8k16.row.col.f32.f16.f16.f32 "
        "{%0,%1,%2,%3}, {%4,%5,%6,%7}, {%8,%9}, {%10,%10,%10,%10};"
        : "=f"(c[0]), "=f"(c[1]), "=f"(c[2]), "=f"(c[3])
        : "r"(a[0]), "r"(a[1]), "r"(a[2]), "r"(a[3]), "r"(b[0]), "r"(b[1]), "f"(0.f));
}

// -------------------- weight prep --------------------------------------------
__global__ void prep_w1_split(const float* __restrict__ W, const float* __restrict__ g,
                              const float* __restrict__ be, const float* __restrict__ m,
                              const float* __restrict__ v, __half* __restrict__ Wp,
                              float* __restrict__ bias) {
    int i = blockIdx.x * blockDim.x + threadIdx.x;
    if (i >= 3 * H1D * IN_F) return;
    int row = i >> 9;
    float a = bn_scale(g[row], v[row]);
    float val = W[i] * a;
    const size_t S = (size_t)3 * H1D * IN_F;
    __half h, l;
    split2(val, h, l);
    Wp[i] = h; Wp[i + S] = l;
    if ((i & (IN_F - 1)) == 0) bias[row] = be[row] - m[row] * a;
}

__global__ void prep_we_split(const float* __restrict__ W, const float* __restrict__ g,
                              const float* __restrict__ be, const float* __restrict__ m,
                              const float* __restrict__ v, __half* __restrict__ Wp,
                              float* __restrict__ bias, int Cout, int K) {
    int i = blockIdx.x * blockDim.x + threadIdx.x;
    if (i >= Cout * K) return;
    int o = i / K;
    int k = i - o * K;
    float acc = 0.f;
#pragma unroll
    for (int s = 0; s < 3; s++) {
        float a = bn_scale(g[s * Cout + o], v[s * Cout + o]);
        acc += a * W[(size_t)(s * Cout + o) * K + k];
    }
    const size_t S = (size_t)Cout * K;
    __half h, l;
    split2(acc, h, l);
    Wp[i] = h; Wp[i + S] = l;
    if (k == 0) {
        float cb = 0.f;
#pragma unroll
        for (int s = 0; s < 3; s++) {
            float a = bn_scale(g[s * Cout + o], v[s * Cout + o]);
            cb += be[s * Cout + o] - m[s * Cout + o] * a;
        }
        bias[o] = cb;
    }
}

// -------------------- activation split / gate --------------------------------
__global__ void split_x_kernel(const float* __restrict__ x, __half* __restrict__ o) {
    int i = blockIdx.x * blockDim.x + threadIdx.x;
    if (i >= N_B * IN_F / 2) return;
    float2 v = ((const float2*)x)[i];
    const size_t S = (size_t)N_B * IN_F;
    __half h0, l0, h1, l1;
    split2(v.x, h0, l0);
    split2(v.y, h1, l1);
    ((__half2*)o)[i] = mkh2(h0, h1);
    ((__half2*)(o + S))[i] = mkh2(l0, l1);
}

// h1 fp32 [b][s*1024+o]  ->  gated+split [lvl][s][b][o]
__global__ void gate1_split(const float* __restrict__ h1, __half* __restrict__ out) {
    int i = blockIdx.x * blockDim.x + threadIdx.x;
    if (i >= N_B * 256) return;
    int b = i >> 8;
    int o4 = i & 255;
    const float4* row = (const float4*)(h1 + (size_t)b * 3072);
    float4 v[3] = {row[o4], row[256 + o4], row[512 + o4]};
    float4 mk;
    mk.x = (v[0].x + v[1].x + v[2].x > 0.f) ? 1.f : 0.f;
    mk.y = (v[0].y + v[1].y + v[2].y > 0.f) ? 1.f : 0.f;
    mk.z = (v[0].z + v[1].z + v[2].z > 0.f) ? 1.f : 0.f;
    mk.w = (v[0].w + v[1].w + v[2].w > 0.f) ? 1.f : 0.f;
    const size_t PL = (size_t)3 * N_B * H1D;
#pragma unroll
    for (int s = 0; s < 3; s++) {
        float gv[4] = {v[s].x * mk.x, v[s].y * mk.y, v[s].z * mk.z, v[s].w * mk.w};
        __half h[4], l[4];
#pragma unroll
        for (int q = 0; q < 4; q++) split2(gv[q], h[q], l[q]);
        size_t base = (size_t)s * N_B * H1D + (size_t)b * H1D + (o4 << 2);
        __half2* p0 = (__half2*)(out + base);
        p0[0] = mkh2(h[0], h[1]); p0[1] = mkh2(h[2], h[3]);
        __half2* p1 = (__half2*)(out + PL + base);
        p1[0] = mkh2(l[0], l[1]); p1[1] = mkh2(l[2], l[3]);
    }
}

// h fp32 plane-major [s][plane]  ->  gated+split [lvl][s][plane]
__global__ void gate_split(const float* __restrict__ h, __half* __restrict__ out,
                           size_t plane) {
    size_t i = (size_t)blockIdx.x * blockDim.x + threadIdx.x;
    size_t q4 = plane >> 2;
    if (i >= q4) return;
    const float4* h4 = (const float4*)h;
    float4 v[3] = {h4[i], h4[i + q4], h4[i + 2 * q4]};
    float4 mk;
    mk.x = (v[0].x + v[1].x + v[2].x > 0.f) ? 1.f : 0.f;
    mk.y = (v[0].y + v[1].y + v[2].y > 0.f) ? 1.f : 0.f;
    mk.z = (v[0].z + v[1].z + v[2].z > 0.f) ? 1.f : 0.f;
    mk.w = (v[0].w + v[1].w + v[2].w > 0.f) ? 1.f : 0.f;
    const size_t PL = 3 * plane;
#pragma unroll
    for (int s = 0; s < 3; s++) {
        float gv[4] = {v[s].x * mk.x, v[s].y * mk.y, v[s].z * mk.z, v[s].w * mk.w};
        __half h0[4], l0[4];
#pragma unroll
        for (int q = 0; q < 4; q++) split2(gv[q], h0[q], l0[q]);
        size_t base = (size_t)s * plane + (i << 2);
        __half2* p0 = (__half2*)(out + base);
        p0[0] = mkh2(h0[0], h0[1]); p0[1] = mkh2(h0[2], h0[3]);
        __half2* p1 = (__half2*)(out + PL + base);
        p1[0] = mkh2(l0[0], l0[1]); p1[1] = mkh2(l0[2], l0[3]);
    }
}

// -------------------- fused 4-product fp16 HMMA GEMM -------------------------
// C[M,N] = (A_hi+A_lo)(B_hi+B_lo)^T + bias = hh + hl + lh + ll (exact to ~2^-22)
// One K sweep. Each 64-wide super-stage loads 4 tiles (A hi/lo, B hi/lo,
// 16KB each = 64KB) and runs all 4 products, reusing A fragments across B
// levels. Double-buffered (128KB smem). tacc chain = 2 kk x 4 products
// (8 mma), RN-drained into fp32 acc.
#define TSZ 16384
#define SUPER (4 * TSZ)
#define SMEM_BYTES (2 * SUPER)

__device__ __forceinline__ void load_tile16(uint32_t dst, const __half* src,
                                            int row0, int KD, int k0, int tid) {
#pragma unroll
    for (int j = 0; j < 4; j++) {
        int id = j * 256 + tid;
        int row = id >> 3, c = id & 7;
        uint32_t d = dst + (row << 7) + (((c ^ row) & 7) << 4);
        const void* s = (const char*)(src + (size_t)(row0 + row) * KD + k0) + (c << 4);
        asm volatile("cp.async.cg.shared.global [%0], [%1], 16;" :: "r"(d), "l"(s));
    }
}

template <int KDIM, int ILV>
__global__ void __launch_bounds__(256, 1)
gemm_fused(const __half* __restrict__ A0, const __half* __restrict__ B0,
           const float* __restrict__ bias, float* __restrict__ C, int M, int N) {
    extern __shared__ __align__(1024) char dsm[];
    const uint32_t Sb = smem_u32(dsm);

    const int tid = threadIdx.x;
    const int wid = tid >> 5;
    const int lane = tid & 31;
    const int warp_m = wid & 1;
    const int warp_n = wid >> 1;
    const int m0 = blockIdx.y * 128;
    const int n0 = blockIdx.x * 128;

    uint32_t aoff[4], boff[2];
#pragma unroll
    for (int mt = 0; mt < 4; mt++)
        aoff[mt] = (uint32_t)(warp_m * 64 + mt * 16 + (lane & 15)) << 7;
#pragma unroll
    for (int np = 0; np < 2; np++)
        boff[np] = (uint32_t)(warp_n * 32 + np * 16 + ((lane >> 4) << 3) + (lane & 7)) << 7;
    const int l7 = lane & 7;
    const int cha = lane >> 4;
    const int chb = (lane >> 3) & 1;

    float acc[4][4][4];
#pragma unroll
    for (int i = 0; i < 4; i++)
#pragma unroll
        for (int j = 0; j < 4; j++)
#pragma unroll
            for (int q = 0; q < 4; q++) acc[i][j][q] = 0.f;

    constexpr int NSUP = KDIM / 64;
    const size_t pas = (size_t)M * KDIM, pbs = (size_t)N * KDIM;

    // prologue: load super-stage 0 into buffer 0
    {
        uint32_t buf = Sb;
#pragma unroll
        for (int lvl = 0; lvl < 2; lvl++) {
            load_tile16(buf + lvl * TSZ, A0 + (size_t)lvl * pas, m0, KDIM, 0, tid);
            load_tile16(buf + (2 + lvl) * TSZ, B0 + (size_t)lvl * pbs, n0, KDIM, 0, tid);
        }
        asm volatile("cp.async.commit_group;" ::: "memory");
    }

    for (int t = 0; t < NSUP; t++) {
        asm volatile("cp.async.wait_group 0;" ::: "memory");
        __syncthreads();

        if (t + 1 < NSUP) {
            uint32_t buf = Sb + ((t + 1) & 1) * SUPER;
            int k0 = (t + 1) * 64;
#pragma unroll
            for (int lvl = 0; lvl < 2; lvl++) {
                load_tile16(buf + lvl * TSZ, A0 + (size_t)lvl * pas, m0, KDIM, k0, tid);
                load_tile16(buf + (2 + lvl) * TSZ, B0 + (size_t)lvl * pbs, n0, KDIM, k0, tid);
            }
            asm volatile("cp.async.commit_group;" ::: "memory");
        }

        const uint32_t Ab = Sb + (t & 1) * SUPER;
        const uint32_t Bb = Ab + 2 * TSZ;

#pragma unroll
        for (int half = 0; half < 2; half++) {
            float tacc[4][4][4];   // zero-written by first mma (mma16816_z)
#pragma unroll
            for (int kk2 = 0; kk2 < 2; kk2++) {
                const int kk = half * 2 + kk2;
                const uint32_t swa = (uint32_t)(((2 * kk + cha) ^ l7) & 7) << 4;
                const uint32_t swb = (uint32_t)(((2 * kk + chb) ^ l7) & 7) << 4;

                uint32_t b[2][2][4];
#pragma unroll
                for (int lvl = 0; lvl < 2; lvl++)
#pragma unroll
                    for (int np = 0; np < 2; np++)
                        lds_x4(b[lvl][np], Bb + lvl * TSZ + boff[np] + swb);

                uint32_t a[4][4];
                // ---- A hi: products hh, hl ----
#pragma unroll
                for (int mt = 0; mt < 4; mt++) lds_x4(a[mt], Ab + 0 * TSZ + aoff[mt] + swa);
                if (kk2 == 0) {
#pragma unroll
                    for (int mt = 0; mt < 4; mt++)
#pragma unroll
                        for (int nt = 0; nt < 4; nt++)
                            mma16816_z(tacc[mt][nt], a[mt], &b[0][nt >> 1][(nt & 1) * 2]);
                } else {
#pragma unroll
                    for (int mt = 0; mt < 4; mt++)
#pragma unroll
                        for (int nt = 0; nt < 4; nt++)
                            mma16816(tacc[mt][nt], a[mt], &b[0][nt >> 1][(nt & 1) * 2]);
                }
#pragma unroll
                for (int mt = 0; mt < 4; mt++)
#pragma unroll
                    for (int nt = 0; nt < 4; nt++)
                        mma16816(tacc[mt][nt], a[mt], &b[1][nt >> 1][(nt & 1) * 2]);
                // ---- A lo: products lh, ll ----
#pragma unroll
                for (int mt = 0; mt < 4; mt++) lds_x4(a[mt], Ab + 1 * TSZ + aoff[mt] + swa);
#pragma unroll
                for (int mt = 0; mt < 4; mt++)
#pragma unroll
                    for (int nt = 0; nt < 4; nt++)
                        mma16816(tacc[mt][nt], a[mt], &b[0][nt >> 1][(nt & 1) * 2]);
#pragma unroll
                for (int mt = 0; mt < 4; mt++)
#pragma unroll
                    for (int nt = 0; nt < 4; nt++)
                        mma16816(tacc[mt][nt], a[mt], &b[1][nt >> 1][(nt & 1) * 2]);
            }
            // RN drain
#pragma unroll
            for (int i = 0; i < 4; i++)
#pragma unroll
                for (int j = 0; j < 4; j++)
#pragma unroll
                    for (int q = 0; q < 4; q++) acc[i][j][q] += tacc[i][j][q];
        }
    }

    // -------------------- epilogue --------------------
#pragma unroll
    for (int mt = 0; mt < 4; mt++) {
#pragma unroll
        for (int nt = 0; nt < 4; nt++) {
            int r0 = m0 + warp_m * 64 + mt * 16 + (lane >> 2);
            int cc = n0 + warp_n * 32 + nt * 8 + (lane & 3) * 2;
            float b0 = bias[cc], b1 = bias[cc + 1];
            float* ac = acc[mt][nt];
            if (!ILV) {
                float2 v0 = make_float2(ac[0] + b0, ac[1] + b1);
                float2 v1 = make_float2(ac[2] + b0, ac[3] + b1);
                *(float2*)(C + (size_t)r0 * N + cc) = v0;
                *(float2*)(C + (size_t)(r0 + 8) * N + cc) = v1;
            } else {
                int s0 = r0 >> 13, bb0 = r0 & 8191;
                int r1 = r0 + 8;
                int s1 = r1 >> 13, bb1 = r1 & 8191;
                C[(size_t)bb0 * (N * 3) + (size_t)cc * 3 + s0] = ac[0] + b0;
                C[(size_t)bb0 * (N * 3) + (size_t)(cc + 1) * 3 + s0] = ac[1] + b1;
                C[(size_t)bb1 * (N * 3) + (size_t)cc * 3 + s1] = ac[2] + b0;
                C[(size_t)bb1 * (N * 3) + (size_t)(cc + 1) * 3 + s1] = ac[3] + b1;
            }
        }
    }
}

// -------------------- launch --------------------------------------------------
extern "C" void kernel_launch(void* const* d_in, const int* in_sizes, int n_in,
                              void* d_out, int out_size) {
    const float* x  = (const float*)d_in[0];
    const float *W1 = (const float*)d_in[1],  *G1 = (const float*)d_in[2],
                *B1 = (const float*)d_in[3],  *M1 = (const float*)d_in[4],
                *V1 = (const float*)d_in[5];
    const float *W2 = (const float*)d_in[6],  *G2 = (const float*)d_in[7],
                *B2 = (const float*)d_in[8],  *M2 = (const float*)d_in[9],
                *V2 = (const float*)d_in[10];
    const float *W3 = (const float*)d_in[11], *G3 = (const float*)d_in[12],
                *B3 = (const float*)d_in[13], *M3 = (const float*)d_in[14],
                *V3 = (const float*)d_in[15];
    const float *W4 = (const float*)d_in[16], *G4 = (const float*)d_in[17],
                *B4 = (const float*)d_in[18], *M4 = (const float*)d_in[19],
                *V4 = (const float*)d_in[20];
    float* out = (float*)d_out;

    __half *xs, *h1s, *h2s, *h3s, *w1p, *w2p, *w3p, *w4p;
    float *h1, *h2, *h3, *c1, *c2, *c3, *c4;
    cudaGetSymbolAddress((void**)&xs, g_xs);
    cudaGetSymbolAddress((void**)&h1, g_h1);
    cudaGetSymbolAddress((void**)&h1s, g_h1s);
    cudaGetSymbolAddress((void**)&h2, g_h2);
    cudaGetSymbolAddress((void**)&h2s, g_h2s);
    cudaGetSymbolAddress((void**)&h3, g_h3);
    cudaGetSymbolAddress((void**)&h3s, g_h3s);
    cudaGetSymbolAddress((void**)&w1p, g_w1p);
    cudaGetSymbolAddress((void**)&w2p, g_w2p);
    cudaGetSymbolAddress((void**)&w3p, g_w3p);
    cudaGetSymbolAddress((void**)&w4p, g_w4p);
    cudaGetSymbolAddress((void**)&c1, g_c1);
    cudaGetSymbolAddress((void**)&c2, g_c2);
    cudaGetSymbolAddress((void**)&c3, g_c3);
    cudaGetSymbolAddress((void**)&c4, g_c4);

    cudaFuncSetAttribute(gemm_fused<512, 0>,  cudaFuncAttributeMaxDynamicSharedMemorySize, SMEM_BYTES);
    cudaFuncSetAttribute(gemm_fused<1024, 0>, cudaFuncAttributeMaxDynamicSharedMemorySize, SMEM_BYTES);
    cudaFuncSetAttribute(gemm_fused<2048, 0>, cudaFuncAttributeMaxDynamicSharedMemorySize, SMEM_BYTES);
    cudaFuncSetAttribute(gemm_fused<1024, 1>, cudaFuncAttributeMaxDynamicSharedMemorySize, SMEM_BYTES);

    const int T = 256;
    split_x_kernel<<<(N_B * IN_F / 2 + T - 1) / T, T>>>(x, xs);
    prep_w1_split<<<(3 * H1D * IN_F + T - 1) / T, T>>>(W1, G1, B1, M1, V1, w1p, c1);
    prep_we_split<<<(H2D * H1D + T - 1) / T, T>>>(W2, G2, B2, M2, V2, w2p, c2, H2D, H1D);
    prep_we_split<<<(H1D * H2D + T - 1) / T, T>>>(W3, G3, B3, M3, V3, w3p, c3, H1D, H2D);
    prep_we_split<<<(IN_F * H1D + T - 1) / T, T>>>(W4, G4, B4, M4, V4, w4p, c4, IN_F, H1D);

    // L1: [8192,512] x [3072,512]^T -> h1 [8192,3072]
    gemm_fused<512, 0><<<dim3(3 * H1D / 128, N_B / 128), T, SMEM_BYTES>>>(xs, w1p, c1, h1, N_B, 3 * H1D);
    gate1_split<<<(N_B * 256 + T - 1) / T, T>>>(h1, h1s);
    // L2: [24576,1024] x [2048,1024]^T
    gemm_fused<1024, 0><<<dim3(H2D / 128, 3 * N_B / 128), T, SMEM_BYTES>>>(h1s, w2p, c2, h2, 3 * N_B, H2D);
    gate_split<<<(N_B * H2D / 4 + T - 1) / T, T>>>(h2, h2s, (size_t)N_B * H2D);
    // L3: [24576,2048] x [1024,2048]^T
    gemm_fused<2048, 0><<<dim3(H1D / 128, 3 * N_B / 128), T, SMEM_BYTES>>>(h2s, w3p, c3, h3, 3 * N_B, H1D);
    gate_split<<<(N_B * H1D / 4 + T - 1) / T, T>>>(h3, h3s, (size_t)N_B * H1D);
    // L4: [24576,1024] x [512,1024]^T -> interleaved out [b][o][s]
    gemm_fused<1024, 1><<<dim3(IN_F / 128, 3 * N_B / 128), T, SMEM_BYTES>>>(h3s, w4p, c4, out, 3 * N_B, IN_F);
}

// round 9
// speedup vs baseline: 2.3181x; 1.2179x over previous
#include <cuda_runtime.h>
#include <cuda_fp16.h>
#include <cstdint>
#include <cstddef>

#define EPSBN 1e-5f
#define N_B   8192
#define IN_F  512
#define H1D   1024
#define H2D   2048

// -------------------- scratch -----------------------------------------------
__device__ __half g_xs [2ULL * N_B * IN_F];
__device__ float  g_h1 [(size_t)N_B * 3 * H1D];
__device__ __half g_h1s[2ULL * 3 * N_B * H1D];
__device__ float  g_h2 [(size_t)3 * N_B * H2D];
__device__ __half g_h2s[2ULL * 3 * N_B * H2D];
__device__ float  g_h3 [(size_t)3 * N_B * H1D];
__device__ __half g_h3s[2ULL * 3 * N_B * H1D];
__device__ __half g_w1p[2ULL * 3 * H1D * IN_F];
__device__ __half g_w2p[2ULL * H2D * H1D];
__device__ __half g_w3p[2ULL * H1D * H2D];
__device__ __half g_w4p[2ULL * IN_F * H1D];
__device__ float g_c1[3 * H1D];
__device__ float g_c2[H2D];
__device__ float g_c3[H1D];
__device__ float g_c4[IN_F];

// -------------------- helpers ------------------------------------------------
__device__ __forceinline__ uint32_t smem_u32(const void* p) {
    uint32_t a;
    asm("{ .reg .u64 t; cvta.to.shared.u64 t, %1; cvt.u32.u64 %0, t; }" : "=r"(a) : "l"(p));
    return a;
}
__device__ __forceinline__ void split2(float x, __half& h, __half& l) {
    h = __float2half_rn(x);
    l = __float2half_rn(x - __half2float(h));
}
__device__ __forceinline__ __half2 mkh2(__half a, __half b) {
    __half2 t; t.x = a; t.y = b; return t;
}
__device__ __forceinline__ float bn_scale(float g, float v) {
    float vv = v + EPSBN;
    float a = rsqrtf(vv);
    return g * (a * (1.5f - 0.5f * vv * a * a));
}
__device__ __forceinline__ void lds_x4(uint32_t* r, uint32_t addr) {
    asm volatile("ldmatrix.sync.aligned.m8n8.x4.shared.b16 {%0,%1,%2,%3}, [%4];"
                 : "=r"(r[0]), "=r"(r[1]), "=r"(r[2]), "=r"(r[3]) : "r"(addr));
}
__device__ __forceinline__ void mma16816(float* c, const uint32_t* a, const uint32_t* b) {
    asm volatile(
        "mma.sync.aligned.m16n8k16.row.col.f32.f16.f16.f32 "
        "{%0,%1,%2,%3}, {%4,%5,%6,%7}, {%8,%9}, {%0,%1,%2,%3};"
        : "+f"(c[0]), "+f"(c[1]), "+f"(c[2]), "+f"(c[3])
        : "r"(a[0]), "r"(a[1]), "r"(a[2]), "r"(a[3]), "r"(b[0]), "r"(b[1]));
}
// first mma of a chain: d = a*b + 0 (avoids tacc pre-zeroing)
__device__ __forceinline__ void mma16816_z(float* c, const uint32_t* a, const uint32_t* b) {
    asm volatile(
        "mma.sync.aligned.m16n8k16.row.col.f32.f16.f16.f32 "
        "{%0,%1,%2,%3}, {%4,%5,%6,%7}, {%8,%9}, {%10,%10,%10,%10};"
        : "=f"(c[0]), "=f"(c[1]), "=f"(c[2]), "=f"(c[3])
        : "r"(a[0]), "r"(a[1]), "r"(a[2]), "r"(a[3]), "r"(b[0]), "r"(b[1]), "f"(0.f));
}

// -------------------- weight prep --------------------------------------------
__global__ void prep_w1_split(const float* __restrict__ W, const float* __restrict__ g,
                              const float* __restrict__ be, const float* __restrict__ m,
                              const float* __restrict__ v, __half* __restrict__ Wp,
                              float* __restrict__ bias) {
    int i = blockIdx.x * blockDim.x + threadIdx.x;
    if (i >= 3 * H1D * IN_F) return;
    int row = i >> 9;
    float a = bn_scale(g[row], v[row]);
    float val = W[i] * a;
    const size_t S = (size_t)3 * H1D * IN_F;
    __half h, l;
    split2(val, h, l);
    Wp[i] = h; Wp[i + S] = l;
    if ((i & (IN_F - 1)) == 0) bias[row] = be[row] - m[row] * a;
}

__global__ void prep_we_split(const float* __restrict__ W, const float* __restrict__ g,
                              const float* __restrict__ be, const float* __restrict__ m,
                              const float* __restrict__ v, __half* __restrict__ Wp,
                              float* __restrict__ bias, int Cout, int K) {
    int i = blockIdx.x * blockDim.x + threadIdx.x;
    if (i >= Cout * K) return;
    int o = i / K;
    int k = i - o * K;
    float acc = 0.f;
#pragma unroll
    for (int s = 0; s < 3; s++) {
        float a = bn_scale(g[s * Cout + o], v[s * Cout + o]);
        acc += a * W[(size_t)(s * Cout + o) * K + k];
    }
    const size_t S = (size_t)Cout * K;
    __half h, l;
    split2(acc, h, l);
    Wp[i] = h; Wp[i + S] = l;
    if (k == 0) {
        float cb = 0.f;
#pragma unroll
        for (int s = 0; s < 3; s++) {
            float a = bn_scale(g[s * Cout + o], v[s * Cout + o]);
            cb += be[s * Cout + o] - m[s * Cout + o] * a;
        }
        bias[o] = cb;
    }
}

// -------------------- activation split / gate --------------------------------
__global__ void split_x_kernel(const float* __restrict__ x, __half* __restrict__ o) {
    int i = blockIdx.x * blockDim.x + threadIdx.x;
    if (i >= N_B * IN_F / 2) return;
    float2 v = ((const float2*)x)[i];
    const size_t S = (size_t)N_B * IN_F;
    __half h0, l0, h1, l1;
    split2(v.x, h0, l0);
    split2(v.y, h1, l1);
    ((__half2*)o)[i] = mkh2(h0, h1);
    ((__half2*)(o + S))[i] = mkh2(l0, l1);
}

// h1 fp32 [b][s*1024+o]  ->  gated+split [lvl][s][b][o]
__global__ void gate1_split(const float* __restrict__ h1, __half* __restrict__ out) {
    int i = blockIdx.x * blockDim.x + threadIdx.x;
    if (i >= N_B * 256) return;
    int b = i >> 8;
    int o4 = i & 255;
    const float4* row = (const float4*)(h1 + (size_t)b * 3072);
    float4 v[3] = {row[o4], row[256 + o4], row[512 + o4]};
    float4 mk;
    mk.x = (v[0].x + v[1].x + v[2].x > 0.f) ? 1.f : 0.f;
    mk.y = (v[0].y + v[1].y + v[2].y > 0.f) ? 1.f : 0.f;
    mk.z = (v[0].z + v[1].z + v[2].z > 0.f) ? 1.f : 0.f;
    mk.w = (v[0].w + v[1].w + v[2].w > 0.f) ? 1.f : 0.f;
    const size_t PL = (size_t)3 * N_B * H1D;
#pragma unroll
    for (int s = 0; s < 3; s++) {
        float gv[4] = {v[s].x * mk.x, v[s].y * mk.y, v[s].z * mk.z, v[s].w * mk.w};
        __half h[4], l[4];
#pragma unroll
        for (int q = 0; q < 4; q++) split2(gv[q], h[q], l[q]);
        size_t base = (size_t)s * N_B * H1D + (size_t)b * H1D + (o4 << 2);
        __half2* p0 = (__half2*)(out + base);
        p0[0] = mkh2(h[0], h[1]); p0[1] = mkh2(h[2], h[3]);
        __half2* p1 = (__half2*)(out + PL + base);
        p1[0] = mkh2(l[0], l[1]); p1[1] = mkh2(l[2], l[3]);
    }
}

// h fp32 plane-major [s][plane]  ->  gated+split [lvl][s][plane]
__global__ void gate_split(const float* __restrict__ h, __half* __restrict__ out,
                           size_t plane) {
    size_t i = (size_t)blockIdx.x * blockDim.x + threadIdx.x;
    size_t q4 = plane >> 2;
    if (i >= q4) return;
    const float4* h4 = (const float4*)h;
    float4 v[3] = {h4[i], h4[i + q4], h4[i + 2 * q4]};
    float4 mk;
    mk.x = (v[0].x + v[1].x + v[2].x > 0.f) ? 1.f : 0.f;
    mk.y = (v[0].y + v[1].y + v[2].y > 0.f) ? 1.f : 0.f;
    mk.z = (v[0].z + v[1].z + v[2].z > 0.f) ? 1.f : 0.f;
    mk.w = (v[0].w + v[1].w + v[2].w > 0.f) ? 1.f : 0.f;
    const size_t PL = 3 * plane;
#pragma unroll
    for (int s = 0; s < 3; s++) {
        float gv[4] = {v[s].x * mk.x, v[s].y * mk.y, v[s].z * mk.z, v[s].w * mk.w};
        __half h0[4], l0[4];
#pragma unroll
        for (int q = 0; q < 4; q++) split2(gv[q], h0[q], l0[q]);
        size_t base = (size_t)s * plane + (i << 2);
        __half2* p0 = (__half2*)(out + base);
        p0[0] = mkh2(h0[0], h0[1]); p0[1] = mkh2(h0[2], h0[3]);
        __half2* p1 = (__half2*)(out + PL + base);
        p1[0] = mkh2(l0[0], l0[1]); p1[1] = mkh2(l0[2], l0[3]);
    }
}

// -------------------- fused 3-product fp16 HMMA GEMM -------------------------
// C[M,N] = hh + hl + lh + bias   (ll dropped: ~2^-22 relative, below fp32
// accumulation noise). One K sweep; each 64-wide super-stage loads 4 tiles
// (A hi/lo, B hi/lo, 16KB each) and runs 3 products, reusing fragments.
// Double-buffered (128KB smem). tacc chain = 2 kk x 3 products (6 mma),
// RN-drained into fp32 acc.
#define TSZ 16384
#define SUPER (4 * TSZ)
#define SMEM_BYTES (2 * SUPER)

__device__ __forceinline__ void load_tile16(uint32_t dst, const __half* src,
                                            int row0, int KD, int k0, int tid) {
#pragma unroll
    for (int j = 0; j < 4; j++) {
        int id = j * 256 + tid;
        int row = id >> 3, c = id & 7;
        uint32_t d = dst + (row << 7) + (((c ^ row) & 7) << 4);
        const void* s = (const char*)(src + (size_t)(row0 + row) * KD + k0) + (c << 4);
        asm volatile("cp.async.cg.shared.global [%0], [%1], 16;" :: "r"(d), "l"(s));
    }
}

template <int KDIM, int ILV>
__global__ void __launch_bounds__(256, 1)
gemm_fused(const __half* __restrict__ A0, const __half* __restrict__ B0,
           const float* __restrict__ bias, float* __restrict__ C, int M, int N) {
    extern __shared__ __align__(1024) char dsm[];
    const uint32_t Sb = smem_u32(dsm);

    const int tid = threadIdx.x;
    const int wid = tid >> 5;
    const int lane = tid & 31;
    const int warp_m = wid & 1;
    const int warp_n = wid >> 1;
    const int m0 = blockIdx.y * 128;
    const int n0 = blockIdx.x * 128;

    uint32_t aoff[4], boff[2];
#pragma unroll
    for (int mt = 0; mt < 4; mt++)
        aoff[mt] = (uint32_t)(warp_m * 64 + mt * 16 + (lane & 15)) << 7;
#pragma unroll
    for (int np = 0; np < 2; np++)
        boff[np] = (uint32_t)(warp_n * 32 + np * 16 + ((lane >> 4) << 3) + (lane & 7)) << 7;
    const int l7 = lane & 7;
    const int cha = lane >> 4;
    const int chb = (lane >> 3) & 1;

    float acc[4][4][4];
#pragma unroll
    for (int i = 0; i < 4; i++)
#pragma unroll
        for (int j = 0; j < 4; j++)
#pragma unroll
            for (int q = 0; q < 4; q++) acc[i][j][q] = 0.f;

    constexpr int NSUP = KDIM / 64;
    const size_t pas = (size_t)M * KDIM, pbs = (size_t)N * KDIM;

    // prologue: load super-stage 0 into buffer 0
    {
        uint32_t buf = Sb;
#pragma unroll
        for (int lvl = 0; lvl < 2; lvl++) {
            load_tile16(buf + lvl * TSZ, A0 + (size_t)lvl * pas, m0, KDIM, 0, tid);
            load_tile16(buf + (2 + lvl) * TSZ, B0 + (size_t)lvl * pbs, n0, KDIM, 0, tid);
        }
        asm volatile("cp.async.commit_group;" ::: "memory");
    }

    for (int t = 0; t < NSUP; t++) {
        asm volatile("cp.async.wait_group 0;" ::: "memory");
        __syncthreads();

        if (t + 1 < NSUP) {
            uint32_t buf = Sb + ((t + 1) & 1) * SUPER;
            int k0 = (t + 1) * 64;
#pragma unroll
            for (int lvl = 0; lvl < 2; lvl++) {
                load_tile16(buf + lvl * TSZ, A0 + (size_t)lvl * pas, m0, KDIM, k0, tid);
                load_tile16(buf + (2 + lvl) * TSZ, B0 + (size_t)lvl * pbs, n0, KDIM, k0, tid);
            }
            asm volatile("cp.async.commit_group;" ::: "memory");
        }

        const uint32_t Ab = Sb + (t & 1) * SUPER;
        const uint32_t Bb = Ab + 2 * TSZ;

#pragma unroll
        for (int half = 0; half < 2; half++) {
            float tacc[4][4][4];   // zero-written by first mma (mma16816_z)
#pragma unroll
            for (int kk2 = 0; kk2 < 2; kk2++) {
                const int kk = half * 2 + kk2;
                const uint32_t swa = (uint32_t)(((2 * kk + cha) ^ l7) & 7) << 4;
                const uint32_t swb = (uint32_t)(((2 * kk + chb) ^ l7) & 7) << 4;

                uint32_t b[2][2][4];
#pragma unroll
                for (int lvl = 0; lvl < 2; lvl++)
#pragma unroll
                    for (int np = 0; np < 2; np++)
                        lds_x4(b[lvl][np], Bb + lvl * TSZ + boff[np] + swb);

                uint32_t a[4][4];
                // ---- A hi: products hh, hl ----
#pragma unroll
                for (int mt = 0; mt < 4; mt++) lds_x4(a[mt], Ab + 0 * TSZ + aoff[mt] + swa);
                if (kk2 == 0) {
#pragma unroll
                    for (int mt = 0; mt < 4; mt++)
#pragma unroll
                        for (int nt = 0; nt < 4; nt++)
                            mma16816_z(tacc[mt][nt], a[mt], &b[0][nt >> 1][(nt & 1) * 2]);
                } else {
#pragma unroll
                    for (int mt = 0; mt < 4; mt++)
#pragma unroll
                        for (int nt = 0; nt < 4; nt++)
                            mma16816(tacc[mt][nt], a[mt], &b[0][nt >> 1][(nt & 1) * 2]);
                }
#pragma unroll
                for (int mt = 0; mt < 4; mt++)
#pragma unroll
                    for (int nt = 0; nt < 4; nt++)
                        mma16816(tacc[mt][nt], a[mt], &b[1][nt >> 1][(nt & 1) * 2]);
                // ---- A lo: product lh ----
#pragma unroll
                for (int mt = 0; mt < 4; mt++) lds_x4(a[mt], Ab + 1 * TSZ + aoff[mt] + swa);
#pragma unroll
                for (int mt = 0; mt < 4; mt++)
#pragma unroll
                    for (int nt = 0; nt < 4; nt++)
                        mma16816(tacc[mt][nt], a[mt], &b[0][nt >> 1][(nt & 1) * 2]);
            }
            // RN drain
#pragma unroll
            for (int i = 0; i < 4; i++)
#pragma unroll
                for (int j = 0; j < 4; j++)
#pragma unroll
                    for (int q = 0; q < 4; q++) acc[i][j][q] += tacc[i][j][q];
        }
    }

    // -------------------- epilogue --------------------
#pragma unroll
    for (int mt = 0; mt < 4; mt++) {
#pragma unroll
        for (int nt = 0; nt < 4; nt++) {
            int r0 = m0 + warp_m * 64 + mt * 16 + (lane >> 2);
            int cc = n0 + warp_n * 32 + nt * 8 + (lane & 3) * 2;
            float b0 = bias[cc], b1 = bias[cc + 1];
            float* ac = acc[mt][nt];
            if (!ILV) {
                float2 v0 = make_float2(ac[0] + b0, ac[1] + b1);
                float2 v1 = make_float2(ac[2] + b0, ac[3] + b1);
                *(float2*)(C + (size_t)r0 * N + cc) = v0;
                *(float2*)(C + (size_t)(r0 + 8) * N + cc) = v1;
            } else {
                int s0 = r0 >> 13, bb0 = r0 & 8191;
                int r1 = r0 + 8;
                int s1 = r1 >> 13, bb1 = r1 & 8191;
                C[(size_t)bb0 * (N * 3) + (size_t)cc * 3 + s0] = ac[0] + b0;
                C[(size_t)bb0 * (N * 3) + (size_t)(cc + 1) * 3 + s0] = ac[1] + b1;
                C[(size_t)bb1 * (N * 3) + (size_t)cc * 3 + s1] = ac[2] + b0;
                C[(size_t)bb1 * (N * 3) + (size_t)(cc + 1) * 3 + s1] = ac[3] + b1;
            }
        }
    }
}

// -------------------- launch --------------------------------------------------
extern "C" void kernel_launch(void* const* d_in, const int* in_sizes, int n_in,
                              void* d_out, int out_size) {
    const float* x  = (const float*)d_in[0];
    const float *W1 = (const float*)d_in[1],  *G1 = (const float*)d_in[2],
                *B1 = (const float*)d_in[3],  *M1 = (const float*)d_in[4],
                *V1 = (const float*)d_in[5];
    const float *W2 = (const float*)d_in[6],  *G2 = (const float*)d_in[7],
                *B2 = (const float*)d_in[8],  *M2 = (const float*)d_in[9],
                *V2 = (const float*)d_in[10];
    const float *W3 = (const float*)d_in[11], *G3 = (const float*)d_in[12],
                *B3 = (const float*)d_in[13], *M3 = (const float*)d_in[14],
                *V3 = (const float*)d_in[15];
    const float *W4 = (const float*)d_in[16], *G4 = (const float*)d_in[17],
                *B4 = (const float*)d_in[18], *M4 = (const float*)d_in[19],
                *V4 = (const float*)d_in[20];
    float* out = (float*)d_out;

    __half *xs, *h1s, *h2s, *h3s, *w1p, *w2p, *w3p, *w4p;
    float *h1, *h2, *h3, *c1, *c2, *c3, *c4;
    cudaGetSymbolAddress((void**)&xs, g_xs);
    cudaGetSymbolAddress((void**)&h1, g_h1);
    cudaGetSymbolAddress((void**)&h1s, g_h1s);
    cudaGetSymbolAddress((void**)&h2, g_h2);
    cudaGetSymbolAddress((void**)&h2s, g_h2s);
    cudaGetSymbolAddress((void**)&h3, g_h3);
    cudaGetSymbolAddress((void**)&h3s, g_h3s);
    cudaGetSymbolAddress((void**)&w1p, g_w1p);
    cudaGetSymbolAddress((void**)&w2p, g_w2p);
    cudaGetSymbolAddress((void**)&w3p, g_w3p);
    cudaGetSymbolAddress((void**)&w4p, g_w4p);
    cudaGetSymbolAddress((void**)&c1, g_c1);
    cudaGetSymbolAddress((void**)&c2, g_c2);
    cudaGetSymbolAddress((void**)&c3, g_c3);
    cudaGetSymbolAddress((void**)&c4, g_c4);

    cudaFuncSetAttribute(gemm_fused<512, 0>,  cudaFuncAttributeMaxDynamicSharedMemorySize, SMEM_BYTES);
    cudaFuncSetAttribute(gemm_fused<1024, 0>, cudaFuncAttributeMaxDynamicSharedMemorySize, SMEM_BYTES);
    cudaFuncSetAttribute(gemm_fused<2048, 0>, cudaFuncAttributeMaxDynamicSharedMemorySize, SMEM_BYTES);
    cudaFuncSetAttribute(gemm_fused<1024, 1>, cudaFuncAttributeMaxDynamicSharedMemorySize, SMEM_BYTES);

    const int T = 256;
    split_x_kernel<<<(N_B * IN_F / 2 + T - 1) / T, T>>>(x, xs);
    prep_w1_split<<<(3 * H1D * IN_F + T - 1) / T, T>>>(W1, G1, B1, M1, V1, w1p, c1);
    prep_we_split<<<(H2D * H1D + T - 1) / T, T>>>(W2, G2, B2, M2, V2, w2p, c2, H2D, H1D);
    prep_we_split<<<(H1D * H2D + T - 1) / T, T>>>(W3, G3, B3, M3, V3, w3p, c3, H1D, H2D);
    prep_we_split<<<(IN_F * H1D + T - 1) / T, T>>>(W4, G4, B4, M4, V4, w4p, c4, IN_F, H1D);

    // L1: [8192,512] x [3072,512]^T -> h1 [8192,3072]
    gemm_fused<512, 0><<<dim3(3 * H1D / 128, N_B / 128), T, SMEM_BYTES>>>(xs, w1p, c1, h1, N_B, 3 * H1D);
    gate1_split<<<(N_B * 256 + T - 1) / T, T>>>(h1, h1s);
    // L2: [24576,1024] x [2048,1024]^T
    gemm_fused<1024, 0><<<dim3(H2D / 128, 3 * N_B / 128), T, SMEM_BYTES>>>(h1s, w2p, c2, h2, 3 * N_B, H2D);
    gate_split<<<(N_B * H2D / 4 + T - 1) / T, T>>>(h2, h2s, (size_t)N_B * H2D);
    // L3: [24576,2048] x [1024,2048]^T
    gemm_fused<2048, 0><<<dim3(H1D / 128, 3 * N_B / 128), T, SMEM_BYTES>>>(h2s, w3p, c3, h3, 3 * N_B, H1D);
    gate_split<<<(N_B * H1D / 4 + T - 1) / T, T>>>(h3, h3s, (size_t)N_B * H1D);
    // L4: [24576,1024] x [512,1024]^T -> interleaved out [b][o][s]
    gemm_fused<1024, 1><<<dim3(IN_F / 128, 3 * N_B / 128), T, SMEM_BYTES>>>(h3s, w4p, c4, out, 3 * N_B, IN_F);
}

// round 10
// speedup vs baseline: 2.3893x; 1.0307x over previous
#include <cuda_runtime.h>
#include <cuda_fp16.h>
#include <cstdint>
#include <cstddef>

#define EPSBN 1e-5f
#define N_B   8192
#define IN_F  512
#define H1D   1024
#define H2D   2048

// -------------------- scratch -----------------------------------------------
__device__ __half g_xs [2ULL * N_B * IN_F];
__device__ float  g_h1 [(size_t)N_B * 3 * H1D];
__device__ __half g_h1s[2ULL * 3 * N_B * H1D];
__device__ float  g_h2 [(size_t)3 * N_B * H2D];
__device__ __half g_h2s[2ULL * 3 * N_B * H2D];
__device__ float  g_h3 [(size_t)3 * N_B * H1D];
__device__ __half g_h3s[2ULL * 3 * N_B * H1D];
__device__ __half g_w1p[2ULL * 3 * H1D * IN_F];
__device__ __half g_w2p[2ULL * H2D * H1D];
__device__ __half g_w3p[2ULL * H1D * H2D];
__device__ __half g_w4p[2ULL * IN_F * H1D];
__device__ float g_c1[3 * H1D];
__device__ float g_c2[H2D];
__device__ float g_c3[H1D];
__device__ float g_c4[IN_F];

// -------------------- helpers ------------------------------------------------
__device__ __forceinline__ uint32_t smem_u32(const void* p) {
    uint32_t a;
    asm("{ .reg .u64 t; cvta.to.shared.u64 t, %1; cvt.u32.u64 %0, t; }" : "=r"(a) : "l"(p));
    return a;
}
__device__ __forceinline__ void split2(float x, __half& h, __half& l) {
    h = __float2half_rn(x);
    l = __float2half_rn(x - __half2float(h));
}
__device__ __forceinline__ __half2 mkh2(__half a, __half b) {
    __half2 t; t.x = a; t.y = b; return t;
}
__device__ __forceinline__ float bn_scale(float g, float v) {
    float vv = v + EPSBN;
    float a = rsqrtf(vv);
    return g * (a * (1.5f - 0.5f * vv * a * a));
}
__device__ __forceinline__ void lds_x4(uint32_t* r, uint32_t addr) {
    asm volatile("ldmatrix.sync.aligned.m8n8.x4.shared.b16 {%0,%1,%2,%3}, [%4];"
                 : "=r"(r[0]), "=r"(r[1]), "=r"(r[2]), "=r"(r[3]) : "r"(addr));
}
__device__ __forceinline__ void mma16816(float* c, const uint32_t* a, const uint32_t* b) {
    asm volatile(
        "mma.sync.aligned.m16n8k16.row.col.f32.f16.f16.f32 "
        "{%0,%1,%2,%3}, {%4,%5,%6,%7}, {%8,%9}, {%0,%1,%2,%3};"
        : "+f"(c[0]), "+f"(c[1]), "+f"(c[2]), "+f"(c[3])
        : "r"(a[0]), "r"(a[1]), "r"(a[2]), "r"(a[3]), "r"(b[0]), "r"(b[1]));
}
// first mma of a chain: d = a*b + 0 (avoids tacc pre-zeroing)
__device__ __forceinline__ void mma16816_z(float* c, const uint32_t* a, const uint32_t* b) {
    asm volatile(
        "mma.sync.aligned.m16n8k16.row.col.f32.f16.f16.f32 "
        "{%0,%1,%2,%3}, {%4,%5,%6,%7}, {%8,%9}, {%10,%10,%10,%10};"
        : "=f"(c[0]), "=f"(c[1]), "=f"(c[2]), "=f"(c[3])
        : "r"(a[0]), "r"(a[1]), "r"(a[2]), "r"(a[3]), "r"(b[0]), "r"(b[1]), "f"(0.f));
}

// -------------------- weight prep --------------------------------------------
__global__ void prep_w1_split(const float* __restrict__ W, const float* __restrict__ g,
                              const float* __restrict__ be, const float* __restrict__ m,
                              const float* __restrict__ v, __half* __restrict__ Wp,
                              float* __restrict__ bias) {
    int i = blockIdx.x * blockDim.x + threadIdx.x;
    if (i >= 3 * H1D * IN_F) return;
    int row = i >> 9;
    float a = bn_scale(g[row], v[row]);
    float val = W[i] * a;
    const size_t S = (size_t)3 * H1D * IN_F;
    __half h, l;
    split2(val, h, l);
    Wp[i] = h; Wp[i + S] = l;
    if ((i & (IN_F - 1)) == 0) bias[row] = be[row] - m[row] * a;
}

__global__ void prep_we_split(const float* __restrict__ W, const float* __restrict__ g,
                              const float* __restrict__ be, const float* __restrict__ m,
                              const float* __restrict__ v, __half* __restrict__ Wp,
                              float* __restrict__ bias, int Cout, int K) {
    int i = blockIdx.x * blockDim.x + threadIdx.x;
    if (i >= Cout * K) return;
    int o = i / K;
    int k = i - o * K;
    float acc = 0.f;
#pragma unroll
    for (int s = 0; s < 3; s++) {
        float a = bn_scale(g[s * Cout + o], v[s * Cout + o]);
        acc += a * W[(size_t)(s * Cout + o) * K + k];
    }
    const size_t S = (size_t)Cout * K;
    __half h, l;
    split2(acc, h, l);
    Wp[i] = h; Wp[i + S] = l;
    if (k == 0) {
        float cb = 0.f;
#pragma unroll
        for (int s = 0; s < 3; s++) {
            float a = bn_scale(g[s * Cout + o], v[s * Cout + o]);
            cb += be[s * Cout + o] - m[s * Cout + o] * a;
        }
        bias[o] = cb;
    }
}

// -------------------- activation split / gate --------------------------------
__global__ void split_x_kernel(const float* __restrict__ x, __half* __restrict__ o) {
    int i = blockIdx.x * blockDim.x + threadIdx.x;
    if (i >= N_B * IN_F / 2) return;
    float2 v = ((const float2*)x)[i];
    const size_t S = (size_t)N_B * IN_F;
    __half h0, l0, h1, l1;
    split2(v.x, h0, l0);
    split2(v.y, h1, l1);
    ((__half2*)o)[i] = mkh2(h0, h1);
    ((__half2*)(o + S))[i] = mkh2(l0, l1);
}

// h1 fp32 [b][s*1024+o]  ->  gated+split [lvl][s][b][o]
__global__ void gate1_split(const float* __restrict__ h1, __half* __restrict__ out) {
    int i = blockIdx.x * blockDim.x + threadIdx.x;
    if (i >= N_B * 256) return;
    int b = i >> 8;
    int o4 = i & 255;
    const float4* row = (const float4*)(h1 + (size_t)b * 3072);
    float4 v[3] = {row[o4], row[256 + o4], row[512 + o4]};
    float4 mk;
    mk.x = (v[0].x + v[1].x + v[2].x > 0.f) ? 1.f : 0.f;
    mk.y = (v[0].y + v[1].y + v[2].y > 0.f) ? 1.f : 0.f;
    mk.z = (v[0].z + v[1].z + v[2].z > 0.f) ? 1.f : 0.f;
    mk.w = (v[0].w + v[1].w + v[2].w > 0.f) ? 1.f : 0.f;
    const size_t PL = (size_t)3 * N_B * H1D;
#pragma unroll
    for (int s = 0; s < 3; s++) {
        float gv[4] = {v[s].x * mk.x, v[s].y * mk.y, v[s].z * mk.z, v[s].w * mk.w};
        __half h[4], l[4];
#pragma unroll
        for (int q = 0; q < 4; q++) split2(gv[q], h[q], l[q]);
        size_t base = (size_t)s * N_B * H1D + (size_t)b * H1D + (o4 << 2);
        __half2* p0 = (__half2*)(out + base);
        p0[0] = mkh2(h[0], h[1]); p0[1] = mkh2(h[2], h[3]);
        __half2* p1 = (__half2*)(out + PL + base);
        p1[0] = mkh2(l[0], l[1]); p1[1] = mkh2(l[2], l[3]);
    }
}

// h fp32 plane-major [s][plane]  ->  gated+split [lvl][s][plane]
__global__ void gate_split(const float* __restrict__ h, __half* __restrict__ out,
                           size_t plane) {
    size_t i = (size_t)blockIdx.x * blockDim.x + threadIdx.x;
    size_t q4 = plane >> 2;
    if (i >= q4) return;
    const float4* h4 = (const float4*)h;
    float4 v[3] = {h4[i], h4[i + q4], h4[i + 2 * q4]};
    float4 mk;
    mk.x = (v[0].x + v[1].x + v[2].x > 0.f) ? 1.f : 0.f;
    mk.y = (v[0].y + v[1].y + v[2].y > 0.f) ? 1.f : 0.f;
    mk.z = (v[0].z + v[1].z + v[2].z > 0.f) ? 1.f : 0.f;
    mk.w = (v[0].w + v[1].w + v[2].w > 0.f) ? 1.f : 0.f;
    const size_t PL = 3 * plane;
#pragma unroll
    for (int s = 0; s < 3; s++) {
        float gv[4] = {v[s].x * mk.x, v[s].y * mk.y, v[s].z * mk.z, v[s].w * mk.w};
        __half h0[4], l0[4];
#pragma unroll
        for (int q = 0; q < 4; q++) split2(gv[q], h0[q], l0[q]);
        size_t base = (size_t)s * plane + (i << 2);
        __half2* p0 = (__half2*)(out + base);
        p0[0] = mkh2(h0[0], h0[1]); p0[1] = mkh2(h0[2], h0[3]);
        __half2* p1 = (__half2*)(out + PL + base);
        p1[0] = mkh2(l0[0], l0[1]); p1[1] = mkh2(l0[2], l0[3]);
    }
}

// -------------------- fused 3-product fp16 HMMA GEMM -------------------------
// C[M,N] = hh + hl + lh + bias   (ll dropped: ~2^-22 relative, below fp32
// accumulation noise). One K sweep; each 64-wide super-stage loads 4 tiles
// (A hi/lo, B hi/lo, 16KB each = 64KB). TRIPLE-buffered (192KB smem),
// cp.async issued 2 stages ahead, wait_group 1 -> loads fully overlapped.
// tacc chain = 4 kk x 3 products (12 mma; validated at 9.1e-4 in R6),
// RN-drained into fp32 acc once per super-stage.
#define TSZ 16384
#define SUPER (4 * TSZ)
#define NBUF 3
#define SMEM_BYTES (NBUF * SUPER)

__device__ __forceinline__ void load_tile16(uint32_t dst, const __half* src,
                                            int row0, int KD, int k0, int tid) {
#pragma unroll
    for (int j = 0; j < 4; j++) {
        int id = j * 256 + tid;
        int row = id >> 3, c = id & 7;
        uint32_t d = dst + (row << 7) + (((c ^ row) & 7) << 4);
        const void* s = (const char*)(src + (size_t)(row0 + row) * KD + k0) + (c << 4);
        asm volatile("cp.async.cg.shared.global [%0], [%1], 16;" :: "r"(d), "l"(s));
    }
}

__device__ __forceinline__ void load_super(uint32_t buf, const __half* A0,
                                           const __half* B0, size_t pas, size_t pbs,
                                           int m0, int n0, int KD, int k0, int tid) {
#pragma unroll
    for (int lvl = 0; lvl < 2; lvl++) {
        load_tile16(buf + lvl * TSZ, A0 + (size_t)lvl * pas, m0, KD, k0, tid);
        load_tile16(buf + (2 + lvl) * TSZ, B0 + (size_t)lvl * pbs, n0, KD, k0, tid);
    }
    asm volatile("cp.async.commit_group;" ::: "memory");
}

template <int KDIM, int ILV>
__global__ void __launch_bounds__(256, 1)
gemm_fused(const __half* __restrict__ A0, const __half* __restrict__ B0,
           const float* __restrict__ bias, float* __restrict__ C, int M, int N) {
    extern __shared__ __align__(1024) char dsm[];
    const uint32_t Sb = smem_u32(dsm);

    const int tid = threadIdx.x;
    const int wid = tid >> 5;
    const int lane = tid & 31;
    const int warp_m = wid & 1;
    const int warp_n = wid >> 1;
    const int m0 = blockIdx.y * 128;
    const int n0 = blockIdx.x * 128;

    uint32_t aoff[4], boff[2];
#pragma unroll
    for (int mt = 0; mt < 4; mt++)
        aoff[mt] = (uint32_t)(warp_m * 64 + mt * 16 + (lane & 15)) << 7;
#pragma unroll
    for (int np = 0; np < 2; np++)
        boff[np] = (uint32_t)(warp_n * 32 + np * 16 + ((lane >> 4) << 3) + (lane & 7)) << 7;
    const int l7 = lane & 7;
    const int cha = lane >> 4;
    const int chb = (lane >> 3) & 1;

    float acc[4][4][4];
#pragma unroll
    for (int i = 0; i < 4; i++)
#pragma unroll
        for (int j = 0; j < 4; j++)
#pragma unroll
            for (int q = 0; q < 4; q++) acc[i][j][q] = 0.f;

    constexpr int NSUP = KDIM / 64;
    const size_t pas = (size_t)M * KDIM, pbs = (size_t)N * KDIM;

    // prologue: load super-stages 0 and 1
    load_super(Sb + 0 * SUPER, A0, B0, pas, pbs, m0, n0, KDIM, 0, tid);
    load_super(Sb + 1 * SUPER, A0, B0, pas, pbs, m0, n0, KDIM, 64, tid);

    int buf_c = 0;   // buffer holding stage t
    for (int t = 0; t < NSUP; t++) {
        if (t + 1 < NSUP) {
            asm volatile("cp.async.wait_group 1;" ::: "memory");
        } else {
            asm volatile("cp.async.wait_group 0;" ::: "memory");
        }
        __syncthreads();

        if (t + 2 < NSUP) {
            int buf_n = buf_c + 2;
            if (buf_n >= NBUF) buf_n -= NBUF;
            load_super(Sb + buf_n * SUPER, A0, B0, pas, pbs, m0, n0, KDIM,
                       (t + 2) * 64, tid);
        }

        const uint32_t Ab = Sb + buf_c * SUPER;
        const uint32_t Bb = Ab + 2 * TSZ;

        float tacc[4][4][4];   // zero-written by first mma (mma16816_z)
#pragma unroll
        for (int kk = 0; kk < 4; kk++) {
            const uint32_t swa = (uint32_t)(((2 * kk + cha) ^ l7) & 7) << 4;
            const uint32_t swb = (uint32_t)(((2 * kk + chb) ^ l7) & 7) << 4;

            uint32_t b[2][2][4];
#pragma unroll
            for (int lvl = 0; lvl < 2; lvl++)
#pragma unroll
                for (int np = 0; np < 2; np++)
                    lds_x4(b[lvl][np], Bb + lvl * TSZ + boff[np] + swb);

            uint32_t a[4][4];
            // ---- A hi: products hh, hl ----
#pragma unroll
            for (int mt = 0; mt < 4; mt++) lds_x4(a[mt], Ab + 0 * TSZ + aoff[mt] + swa);
            if (kk == 0) {
#pragma unroll
                for (int mt = 0; mt < 4; mt++)
#pragma unroll
                    for (int nt = 0; nt < 4; nt++)
                        mma16816_z(tacc[mt][nt], a[mt], &b[0][nt >> 1][(nt & 1) * 2]);
            } else {
#pragma unroll
                for (int mt = 0; mt < 4; mt++)
#pragma unroll
                    for (int nt = 0; nt < 4; nt++)
                        mma16816(tacc[mt][nt], a[mt], &b[0][nt >> 1][(nt & 1) * 2]);
            }
#pragma unroll
            for (int mt = 0; mt < 4; mt++)
#pragma unroll
                for (int nt = 0; nt < 4; nt++)
                    mma16816(tacc[mt][nt], a[mt], &b[1][nt >> 1][(nt & 1) * 2]);
            // ---- A lo: product lh ----
#pragma unroll
            for (int mt = 0; mt < 4; mt++) lds_x4(a[mt], Ab + 1 * TSZ + aoff[mt] + swa);
#pragma unroll
            for (int mt = 0; mt < 4; mt++)
#pragma unroll
                for (int nt = 0; nt < 4; nt++)
                    mma16816(tacc[mt][nt], a[mt], &b[0][nt >> 1][(nt & 1) * 2]);
        }
        // RN drain, once per super-stage (chain 12)
#pragma unroll
        for (int i = 0; i < 4; i++)
#pragma unroll
            for (int j = 0; j < 4; j++)
#pragma unroll
                for (int q = 0; q < 4; q++) acc[i][j][q] += tacc[i][j][q];

        buf_c++;
        if (buf_c >= NBUF) buf_c -= NBUF;
    }

    // -------------------- epilogue --------------------
#pragma unroll
    for (int mt = 0; mt < 4; mt++) {
#pragma unroll
        for (int nt = 0; nt < 4; nt++) {
            int r0 = m0 + warp_m * 64 + mt * 16 + (lane >> 2);
            int cc = n0 + warp_n * 32 + nt * 8 + (lane & 3) * 2;
            float b0 = bias[cc], b1 = bias[cc + 1];
            float* ac = acc[mt][nt];
            if (!ILV) {
                float2 v0 = make_float2(ac[0] + b0, ac[1] + b1);
                float2 v1 = make_float2(ac[2] + b0, ac[3] + b1);
                *(float2*)(C + (size_t)r0 * N + cc) = v0;
                *(float2*)(C + (size_t)(r0 + 8) * N + cc) = v1;
            } else {
                int s0 = r0 >> 13, bb0 = r0 & 8191;
                int r1 = r0 + 8;
                int s1 = r1 >> 13, bb1 = r1 & 8191;
                C[(size_t)bb0 * (N * 3) + (size_t)cc * 3 + s0] = ac[0] + b0;
                C[(size_t)bb0 * (N * 3) + (size_t)(cc + 1) * 3 + s0] = ac[1] + b1;
                C[(size_t)bb1 * (N * 3) + (size_t)cc * 3 + s1] = ac[2] + b0;
                C[(size_t)bb1 * (N * 3) + (size_t)(cc + 1) * 3 + s1] = ac[3] + b1;
            }
        }
    }
}

// -------------------- launch --------------------------------------------------
extern "C" void kernel_launch(void* const* d_in, const int* in_sizes, int n_in,
                              void* d_out, int out_size) {
    const float* x  = (const float*)d_in[0];
    const float *W1 = (const float*)d_in[1],  *G1 = (const float*)d_in[2],
                *B1 = (const float*)d_in[3],  *M1 = (const float*)d_in[4],
                *V1 = (const float*)d_in[5];
    const float *W2 = (const float*)d_in[6],  *G2 = (const float*)d_in[7],
                *B2 = (const float*)d_in[8],  *M2 = (const float*)d_in[9],
                *V2 = (const float*)d_in[10];
    const float *W3 = (const float*)d_in[11], *G3 = (const float*)d_in[12],
                *B3 = (const float*)d_in[13], *M3 = (const float*)d_in[14],
                *V3 = (const float*)d_in[15];
    const float *W4 = (const float*)d_in[16], *G4 = (const float*)d_in[17],
                *B4 = (const float*)d_in[18], *M4 = (const float*)d_in[19],
                *V4 = (const float*)d_in[20];
    float* out = (float*)d_out;

    __half *xs, *h1s, *h2s, *h3s, *w1p, *w2p, *w3p, *w4p;
    float *h1, *h2, *h3, *c1, *c2, *c3, *c4;
    cudaGetSymbolAddress((void**)&xs, g_xs);
    cudaGetSymbolAddress((void**)&h1, g_h1);
    cudaGetSymbolAddress((void**)&h1s, g_h1s);
    cudaGetSymbolAddress((void**)&h2, g_h2);
    cudaGetSymbolAddress((void**)&h2s, g_h2s);
    cudaGetSymbolAddress((void**)&h3, g_h3);
    cudaGetSymbolAddress((void**)&h3s, g_h3s);
    cudaGetSymbolAddress((void**)&w1p, g_w1p);
    cudaGetSymbolAddress((void**)&w2p, g_w2p);
    cudaGetSymbolAddress((void**)&w3p, g_w3p);
    cudaGetSymbolAddress((void**)&w4p, g_w4p);
    cudaGetSymbolAddress((void**)&c1, g_c1);
    cudaGetSymbolAddress((void**)&c2, g_c2);
    cudaGetSymbolAddress((void**)&c3, g_c3);
    cudaGetSymbolAddress((void**)&c4, g_c4);

    cudaFuncSetAttribute(gemm_fused<512, 0>,  cudaFuncAttributeMaxDynamicSharedMemorySize, SMEM_BYTES);
    cudaFuncSetAttribute(gemm_fused<1024, 0>, cudaFuncAttributeMaxDynamicSharedMemorySize, SMEM_BYTES);
    cudaFuncSetAttribute(gemm_fused<2048, 0>, cudaFuncAttributeMaxDynamicSharedMemorySize, SMEM_BYTES);
    cudaFuncSetAttribute(gemm_fused<1024, 1>, cudaFuncAttributeMaxDynamicSharedMemorySize, SMEM_BYTES);

    const int T = 256;
    split_x_kernel<<<(N_B * IN_F / 2 + T - 1) / T, T>>>(x, xs);
    prep_w1_split<<<(3 * H1D * IN_F + T - 1) / T, T>>>(W1, G1, B1, M1, V1, w1p, c1);
    prep_we_split<<<(H2D * H1D + T - 1) / T, T>>>(W2, G2, B2, M2, V2, w2p, c2, H2D, H1D);
    prep_we_split<<<(H1D * H2D + T - 1) / T, T>>>(W3, G3, B3, M3, V3, w3p, c3, H1D, H2D);
    prep_we_split<<<(IN_F * H1D + T - 1) / T, T>>>(W4, G4, B4, M4, V4, w4p, c4, IN_F, H1D);

    // L1: [8192,512] x [3072,512]^T -> h1 [8192,3072]
    gemm_fused<512, 0><<<dim3(3 * H1D / 128, N_B / 128), T, SMEM_BYTES>>>(xs, w1p, c1, h1, N_B, 3 * H1D);
    gate1_split<<<(N_B * 256 + T - 1) / T, T>>>(h1, h1s);
    // L2: [24576,1024] x [2048,1024]^T
    gemm_fused<1024, 0><<<dim3(H2D / 128, 3 * N_B / 128), T, SMEM_BYTES>>>(h1s, w2p, c2, h2, 3 * N_B, H2D);
    gate_split<<<(N_B * H2D / 4 + T - 1) / T, T>>>(h2, h2s, (size_t)N_B * H2D);
    // L3: [24576,2048] x [1024,2048]^T
    gemm_fused<2048, 0><<<dim3(H1D / 128, 3 * N_B / 128), T, SMEM_BYTES>>>(h2s, w3p, c3, h3, 3 * N_B, H1D);
    gate_split<<<(N_B * H1D / 4 + T - 1) / T, T>>>(h3, h3s, (size_t)N_B * H1D);
    // L4: [24576,1024] x [512,1024]^T -> interleaved out [b][o][s]
    gemm_fused<1024, 1><<<dim3(IN_F / 128, 3 * N_B / 128), T, SMEM_BYTES>>>(h3s, w4p, c4, out, 3 * N_B, IN_F);
}

// round 11
// speedup vs baseline: 2.3987x; 1.0039x over previous
#include <cuda_runtime.h>
#include <cuda_fp16.h>
#include <cstdint>
#include <cstddef>

#define EPSBN 1e-5f
#define N_B   8192
#define IN_F  512
#define H1D   1024
#define H2D   2048

// -------------------- scratch -----------------------------------------------
__device__ __align__(16) __half g_xs [2ULL * N_B * IN_F];
__device__ __align__(16) float  g_h1 [(size_t)N_B * 3 * H1D];
__device__ __align__(16) __half g_h1s[2ULL * 3 * N_B * H1D];
__device__ __align__(16) float  g_h2 [(size_t)3 * N_B * H2D];
__device__ __align__(16) __half g_h2s[2ULL * 3 * N_B * H2D];
__device__ __align__(16) float  g_h3 [(size_t)3 * N_B * H1D];
__device__ __align__(16) __half g_h3s[2ULL * 3 * N_B * H1D];
__device__ __align__(16) __half g_w1p[2ULL * 3 * H1D * IN_F];
__device__ __align__(16) __half g_w2p[2ULL * H2D * H1D];
__device__ __align__(16) __half g_w3p[2ULL * H1D * H2D];
__device__ __align__(16) __half g_w4p[2ULL * IN_F * H1D];
__device__ float g_c1[3 * H1D];
__device__ float g_c2[H2D];
__device__ float g_c3[H1D];
__device__ float g_c4[IN_F];

// -------------------- helpers ------------------------------------------------
__device__ __forceinline__ uint32_t smem_u32(const void* p) {
    uint32_t a;
    asm("{ .reg .u64 t; cvta.to.shared.u64 t, %1; cvt.u32.u64 %0, t; }" : "=r"(a) : "l"(p));
    return a;
}
__device__ __forceinline__ uint32_t h2u(__half2 h) { return *(uint32_t*)&h; }
// packed split: 2 elements -> (hi half2, lo half2), RN everywhere
__device__ __forceinline__ void split2x2(float x0, float x1, uint32_t& hi, uint32_t& lo) {
    __half2 h = __floats2half2_rn(x0, x1);
    float2 f = __half22float2(h);
    __half2 l = __floats2half2_rn(x0 - f.x, x1 - f.y);
    hi = h2u(h); lo = h2u(l);
}
__device__ __forceinline__ float bn_scale(float g, float v) {
    float vv = v + EPSBN;
    float a = rsqrtf(vv);
    return g * (a * (1.5f - 0.5f * vv * a * a));
}
__device__ __forceinline__ void lds_x4(uint32_t* r, uint32_t addr) {
    asm volatile("ldmatrix.sync.aligned.m8n8.x4.shared.b16 {%0,%1,%2,%3}, [%4];"
                 : "=r"(r[0]), "=r"(r[1]), "=r"(r[2]), "=r"(r[3]) : "r"(addr));
}
__device__ __forceinline__ void mma16816(float* c, const uint32_t* a, const uint32_t* b) {
    asm volatile(
        "mma.sync.aligned.m16n8k16.row.col.f32.f16.f16.f32 "
        "{%0,%1,%2,%3}, {%4,%5,%6,%7}, {%8,%9}, {%0,%1,%2,%3};"
        : "+f"(c[0]), "+f"(c[1]), "+f"(c[2]), "+f"(c[3])
        : "r"(a[0]), "r"(a[1]), "r"(a[2]), "r"(a[3]), "r"(b[0]), "r"(b[1]));
}
__device__ __forceinline__ void mma16816_z(float* c, const uint32_t* a, const uint32_t* b) {
    asm volatile(
        "mma.sync.aligned.m16n8k16.row.col.f32.f16.f16.f32 "
        "{%0,%1,%2,%3}, {%4,%5,%6,%7}, {%8,%9}, {%10,%10,%10,%10};"
        : "=f"(c[0]), "=f"(c[1]), "=f"(c[2]), "=f"(c[3])
        : "r"(a[0]), "r"(a[1]), "r"(a[2]), "r"(a[3]), "r"(b[0]), "r"(b[1]), "f"(0.f));
}

// -------------------- weight prep (vectorized by 2 along K) ------------------
__global__ void prep_w1_split(const float* __restrict__ W, const float* __restrict__ g,
                              const float* __restrict__ be, const float* __restrict__ m,
                              const float* __restrict__ v, __half* __restrict__ Wp,
                              float* __restrict__ bias) {
    int t = blockIdx.x * blockDim.x + threadIdx.x;
    if (t >= 3 * H1D * IN_F / 2) return;
    int i = 2 * t;
    int row = i >> 9;
    float a = bn_scale(g[row], v[row]);
    float2 w = *(const float2*)&W[i];
    const size_t S = (size_t)3 * H1D * IN_F;
    uint32_t hi, lo;
    split2x2(w.x * a, w.y * a, hi, lo);
    *(uint32_t*)&Wp[i] = hi;
    *(uint32_t*)&Wp[i + S] = lo;
    if ((i & (IN_F - 1)) == 0) bias[row] = be[row] - m[row] * a;
}

__global__ void prep_we_split(const float* __restrict__ W, const float* __restrict__ g,
                              const float* __restrict__ be, const float* __restrict__ m,
                              const float* __restrict__ v, __half* __restrict__ Wp,
                              float* __restrict__ bias, int Cout, int K) {
    int t = blockIdx.x * blockDim.x + threadIdx.x;
    if (t >= Cout * K / 2) return;
    int i = 2 * t;
    int o = i / K;
    int k = i - o * K;
    float ax = 0.f, ay = 0.f;
#pragma unroll
    for (int s = 0; s < 3; s++) {
        float a = bn_scale(g[s * Cout + o], v[s * Cout + o]);
        float2 w = *(const float2*)&W[(size_t)(s * Cout + o) * K + k];
        ax += a * w.x;
        ay += a * w.y;
    }
    const size_t S = (size_t)Cout * K;
    uint32_t hi, lo;
    split2x2(ax, ay, hi, lo);
    *(uint32_t*)&Wp[i] = hi;
    *(uint32_t*)&Wp[i + S] = lo;
    if (k == 0) {
        float cb = 0.f;
#pragma unroll
        for (int s = 0; s < 3; s++) {
            float a = bn_scale(g[s * Cout + o], v[s * Cout + o]);
            cb += be[s * Cout + o] - m[s * Cout + o] * a;
        }
        bias[o] = cb;
    }
}

// -------------------- activation split / gate --------------------------------
// x split: 4 elems/thread, packed cvt, 8B stores
__global__ void split_x_kernel(const float* __restrict__ x, __half* __restrict__ o) {
    int i = blockIdx.x * blockDim.x + threadIdx.x;
    if (i >= N_B * IN_F / 4) return;
    float4 v = ((const float4*)x)[i];
    const size_t S = (size_t)N_B * IN_F;
    uint2 hi, lo;
    split2x2(v.x, v.y, hi.x, lo.x);
    split2x2(v.z, v.w, hi.y, lo.y);
    ((uint2*)o)[i] = hi;
    ((uint2*)(o + S))[i] = lo;
}

// h1 fp32 [b][s*1024+o] -> gated+split [lvl][s][b][o]; 8 elems/plane/thread
__global__ void gate1_split(const float* __restrict__ h1, __half* __restrict__ out) {
    int i = blockIdx.x * blockDim.x + threadIdx.x;
    if (i >= N_B * 128) return;
    int b = i >> 7;
    int o8 = i & 127;
    const float4* row = (const float4*)(h1 + (size_t)b * 3072);
    float4 va[3], vb[3];
#pragma unroll
    for (int s = 0; s < 3; s++) {
        va[s] = row[s * 256 + o8 * 2];
        vb[s] = row[s * 256 + o8 * 2 + 1];
    }
    float4 ma, mb;
    ma.x = (va[0].x + va[1].x + va[2].x > 0.f) ? 1.f : 0.f;
    ma.y = (va[0].y + va[1].y + va[2].y > 0.f) ? 1.f : 0.f;
    ma.z = (va[0].z + va[1].z + va[2].z > 0.f) ? 1.f : 0.f;
    ma.w = (va[0].w + va[1].w + va[2].w > 0.f) ? 1.f : 0.f;
    mb.x = (vb[0].x + vb[1].x + vb[2].x > 0.f) ? 1.f : 0.f;
    mb.y = (vb[0].y + vb[1].y + vb[2].y > 0.f) ? 1.f : 0.f;
    mb.z = (vb[0].z + vb[1].z + vb[2].z > 0.f) ? 1.f : 0.f;
    mb.w = (vb[0].w + vb[1].w + vb[2].w > 0.f) ? 1.f : 0.f;
    const size_t PL = (size_t)3 * N_B * H1D;
#pragma unroll
    for (int s = 0; s < 3; s++) {
        uint4 hi, lo;
        split2x2(va[s].x * ma.x, va[s].y * ma.y, hi.x, lo.x);
        split2x2(va[s].z * ma.z, va[s].w * ma.w, hi.y, lo.y);
        split2x2(vb[s].x * mb.x, vb[s].y * mb.y, hi.z, lo.z);
        split2x2(vb[s].z * mb.z, vb[s].w * mb.w, hi.w, lo.w);
        size_t base = (size_t)s * N_B * H1D + (size_t)b * H1D + (o8 << 3);
        *(uint4*)(out + base) = hi;
        *(uint4*)(out + PL + base) = lo;
    }
}

// h fp32 plane-major [s][plane] -> gated+split [lvl][s][plane]; 8 elems/plane/thread
__global__ void gate_split(const float* __restrict__ h, __half* __restrict__ out,
                           size_t plane) {
    size_t i = (size_t)blockIdx.x * blockDim.x + threadIdx.x;
    size_t q8 = plane >> 3;
    if (i >= q8) return;
    const float4* h4 = (const float4*)h;
    size_t p4 = plane >> 2;
    size_t i2 = i * 2;
    float4 va[3], vb[3];
#pragma unroll
    for (int s = 0; s < 3; s++) {
        va[s] = h4[i2 + (size_t)s * p4];
        vb[s] = h4[i2 + 1 + (size_t)s * p4];
    }
    float4 ma, mb;
    ma.x = (va[0].x + va[1].x + va[2].x > 0.f) ? 1.f : 0.f;
    ma.y = (va[0].y + va[1].y + va[2].y > 0.f) ? 1.f : 0.f;
    ma.z = (va[0].z + va[1].z + va[2].z > 0.f) ? 1.f : 0.f;
    ma.w = (va[0].w + va[1].w + va[2].w > 0.f) ? 1.f : 0.f;
    mb.x = (vb[0].x + vb[1].x + vb[2].x > 0.f) ? 1.f : 0.f;
    mb.y = (vb[0].y + vb[1].y + vb[2].y > 0.f) ? 1.f : 0.f;
    mb.z = (vb[0].z + vb[1].z + vb[2].z > 0.f) ? 1.f : 0.f;
    mb.w = (vb[0].w + vb[1].w + vb[2].w > 0.f) ? 1.f : 0.f;
    const size_t PL = 3 * plane;
#pragma unroll
    for (int s = 0; s < 3; s++) {
        uint4 hi, lo;
        split2x2(va[s].x * ma.x, va[s].y * ma.y, hi.x, lo.x);
        split2x2(va[s].z * ma.z, va[s].w * ma.w, hi.y, lo.y);
        split2x2(vb[s].x * mb.x, vb[s].y * mb.y, hi.z, lo.z);
        split2x2(vb[s].z * mb.z, vb[s].w * mb.w, hi.w, lo.w);
        size_t base = (size_t)s * plane + (i << 3);
        *(uint4*)(out + base) = hi;
        *(uint4*)(out + PL + base) = lo;
    }
}

// -------------------- fused 3-product fp16 HMMA GEMM -------------------------
// C = hh + hl + lh + bias. Triple-buffered 64KB super-stages (192KB smem),
// cp.async 2 ahead, wait_group 1. tacc chain = 12 mma, RN drain per stage.
#define TSZ 16384
#define SUPER (4 * TSZ)
#define NBUF 3
#define SMEM_BYTES (NBUF * SUPER)

__device__ __forceinline__ void load_tile16(uint32_t dst, const __half* src,
                                            int row0, int KD, int k0, int tid) {
#pragma unroll
    for (int j = 0; j < 4; j++) {
        int id = j * 256 + tid;
        int row = id >> 3, c = id & 7;
        uint32_t d = dst + (row << 7) + (((c ^ row) & 7) << 4);
        const void* s = (const char*)(src + (size_t)(row0 + row) * KD + k0) + (c << 4);
        asm volatile("cp.async.cg.shared.global [%0], [%1], 16;" :: "r"(d), "l"(s));
    }
}

__device__ __forceinline__ void load_super(uint32_t buf, const __half* A0,
                                           const __half* B0, size_t pas, size_t pbs,
                                           int m0, int n0, int KD, int k0, int tid) {
#pragma unroll
    for (int lvl = 0; lvl < 2; lvl++) {
        load_tile16(buf + lvl * TSZ, A0 + (size_t)lvl * pas, m0, KD, k0, tid);
        load_tile16(buf + (2 + lvl) * TSZ, B0 + (size_t)lvl * pbs, n0, KD, k0, tid);
    }
    asm volatile("cp.async.commit_group;" ::: "memory");
}

template <int KDIM, int ILV>
__global__ void __launch_bounds__(256, 1)
gemm_fused(const __half* __restrict__ A0, const __half* __restrict__ B0,
           const float* __restrict__ bias, float* __restrict__ C, int M, int N) {
    extern __shared__ __align__(1024) char dsm[];
    const uint32_t Sb = smem_u32(dsm);

    const int tid = threadIdx.x;
    const int wid = tid >> 5;
    const int lane = tid & 31;
    const int warp_m = wid & 1;
    const int warp_n = wid >> 1;
    const int m0 = blockIdx.y * 128;
    const int n0 = blockIdx.x * 128;

    uint32_t aoff[4], boff[2];
#pragma unroll
    for (int mt = 0; mt < 4; mt++)
        aoff[mt] = (uint32_t)(warp_m * 64 + mt * 16 + (lane & 15)) << 7;
#pragma unroll
    for (int np = 0; np < 2; np++)
        boff[np] = (uint32_t)(warp_n * 32 + np * 16 + ((lane >> 4) << 3) + (lane & 7)) << 7;
    const int l7 = lane & 7;
    const int cha = lane >> 4;
    const int chb = (lane >> 3) & 1;

    float acc[4][4][4];
#pragma unroll
    for (int i = 0; i < 4; i++)
#pragma unroll
        for (int j = 0; j < 4; j++)
#pragma unroll
            for (int q = 0; q < 4; q++) acc[i][j][q] = 0.f;

    constexpr int NSUP = KDIM / 64;
    const size_t pas = (size_t)M * KDIM, pbs = (size_t)N * KDIM;

    load_super(Sb + 0 * SUPER, A0, B0, pas, pbs, m0, n0, KDIM, 0, tid);
    load_super(Sb + 1 * SUPER, A0, B0, pas, pbs, m0, n0, KDIM, 64, tid);

    int buf_c = 0;
    for (int t = 0; t < NSUP; t++) {
        if (t + 1 < NSUP) {
            asm volatile("cp.async.wait_group 1;" ::: "memory");
        } else {
            asm volatile("cp.async.wait_group 0;" ::: "memory");
        }
        __syncthreads();

        if (t + 2 < NSUP) {
            int buf_n = buf_c + 2;
            if (buf_n >= NBUF) buf_n -= NBUF;
            load_super(Sb + buf_n * SUPER, A0, B0, pas, pbs, m0, n0, KDIM,
                       (t + 2) * 64, tid);
        }

        const uint32_t Ab = Sb + buf_c * SUPER;
        const uint32_t Bb = Ab + 2 * TSZ;

        float tacc[4][4][4];
#pragma unroll
        for (int kk = 0; kk < 4; kk++) {
            const uint32_t swa = (uint32_t)(((2 * kk + cha) ^ l7) & 7) << 4;
            const uint32_t swb = (uint32_t)(((2 * kk + chb) ^ l7) & 7) << 4;

            uint32_t b[2][2][4];
#pragma unroll
            for (int lvl = 0; lvl < 2; lvl++)
#pragma unroll
                for (int np = 0; np < 2; np++)
                    lds_x4(b[lvl][np], Bb + lvl * TSZ + boff[np] + swb);

            uint32_t a[4][4];
#pragma unroll
            for (int mt = 0; mt < 4; mt++) lds_x4(a[mt], Ab + 0 * TSZ + aoff[mt] + swa);
            if (kk == 0) {
#pragma unroll
                for (int mt = 0; mt < 4; mt++)
#pragma unroll
                    for (int nt = 0; nt < 4; nt++)
                        mma16816_z(tacc[mt][nt], a[mt], &b[0][nt >> 1][(nt & 1) * 2]);
            } else {
#pragma unroll
                for (int mt = 0; mt < 4; mt++)
#pragma unroll
                    for (int nt = 0; nt < 4; nt++)
                        mma16816(tacc[mt][nt], a[mt], &b[0][nt >> 1][(nt & 1) * 2]);
            }
#pragma unroll
            for (int mt = 0; mt < 4; mt++)
#pragma unroll
                for (int nt = 0; nt < 4; nt++)
                    mma16816(tacc[mt][nt], a[mt], &b[1][nt >> 1][(nt & 1) * 2]);
#pragma unroll
            for (int mt = 0; mt < 4; mt++) lds_x4(a[mt], Ab + 1 * TSZ + aoff[mt] + swa);
#pragma unroll
            for (int mt = 0; mt < 4; mt++)
#pragma unroll
                for (int nt = 0; nt < 4; nt++)
                    mma16816(tacc[mt][nt], a[mt], &b[0][nt >> 1][(nt & 1) * 2]);
        }
#pragma unroll
        for (int i = 0; i < 4; i++)
#pragma unroll
            for (int j = 0; j < 4; j++)
#pragma unroll
                for (int q = 0; q < 4; q++) acc[i][j][q] += tacc[i][j][q];

        buf_c++;
        if (buf_c >= NBUF) buf_c -= NBUF;
    }

    // -------------------- epilogue --------------------
#pragma unroll
    for (int mt = 0; mt < 4; mt++) {
#pragma unroll
        for (int nt = 0; nt < 4; nt++) {
            int r0 = m0 + warp_m * 64 + mt * 16 + (lane >> 2);
            int cc = n0 + warp_n * 32 + nt * 8 + (lane & 3) * 2;
            float b0 = bias[cc], b1 = bias[cc + 1];
            float* ac = acc[mt][nt];
            if (!ILV) {
                float2 v0 = make_float2(ac[0] + b0, ac[1] + b1);
                float2 v1 = make_float2(ac[2] + b0, ac[3] + b1);
                *(float2*)(C + (size_t)r0 * N + cc) = v0;
                *(float2*)(C + (size_t)(r0 + 8) * N + cc) = v1;
            } else {
                int s0 = r0 >> 13, bb0 = r0 & 8191;
                int r1 = r0 + 8;
                int s1 = r1 >> 13, bb1 = r1 & 8191;
                C[(size_t)bb0 * (N * 3) + (size_t)cc * 3 + s0] = ac[0] + b0;
                C[(size_t)bb0 * (N * 3) + (size_t)(cc + 1) * 3 + s0] = ac[1] + b1;
                C[(size_t)bb1 * (N * 3) + (size_t)cc * 3 + s1] = ac[2] + b0;
                C[(size_t)bb1 * (N * 3) + (size_t)(cc + 1) * 3 + s1] = ac[3] + b1;
            }
        }
    }
}

// -------------------- launch --------------------------------------------------
extern "C" void kernel_launch(void* const* d_in, const int* in_sizes, int n_in,
                              void* d_out, int out_size) {
    const float* x  = (const float*)d_in[0];
    const float *W1 = (const float*)d_in[1],  *G1 = (const float*)d_in[2],
                *B1 = (const float*)d_in[3],  *M1 = (const float*)d_in[4],
                *V1 = (const float*)d_in[5];
    const float *W2 = (const float*)d_in[6],  *G2 = (const float*)d_in[7],
                *B2 = (const float*)d_in[8],  *M2 = (const float*)d_in[9],
                *V2 = (const float*)d_in[10];
    const float *W3 = (const float*)d_in[11], *G3 = (const float*)d_in[12],
                *B3 = (const float*)d_in[13], *M3 = (const float*)d_in[14],
                *V3 = (const float*)d_in[15];
    const float *W4 = (const float*)d_in[16], *G4 = (const float*)d_in[17],
                *B4 = (const float*)d_in[18], *M4 = (const float*)d_in[19],
                *V4 = (const float*)d_in[20];
    float* out = (float*)d_out;

    __half *xs, *h1s, *h2s, *h3s, *w1p, *w2p, *w3p, *w4p;
    float *h1, *h2, *h3, *c1, *c2, *c3, *c4;
    cudaGetSymbolAddress((void**)&xs, g_xs);
    cudaGetSymbolAddress((void**)&h1, g_h1);
    cudaGetSymbolAddress((void**)&h1s, g_h1s);
    cudaGetSymbolAddress((void**)&h2, g_h2);
    cudaGetSymbolAddress((void**)&h2s, g_h2s);
    cudaGetSymbolAddress((void**)&h3, g_h3);
    cudaGetSymbolAddress((void**)&h3s, g_h3s);
    cudaGetSymbolAddress((void**)&w1p, g_w1p);
    cudaGetSymbolAddress((void**)&w2p, g_w2p);
    cudaGetSymbolAddress((void**)&w3p, g_w3p);
    cudaGetSymbolAddress((void**)&w4p, g_w4p);
    cudaGetSymbolAddress((void**)&c1, g_c1);
    cudaGetSymbolAddress((void**)&c2, g_c2);
    cudaGetSymbolAddress((void**)&c3, g_c3);
    cudaGetSymbolAddress((void**)&c4, g_c4);

    cudaFuncSetAttribute(gemm_fused<512, 0>,  cudaFuncAttributeMaxDynamicSharedMemorySize, SMEM_BYTES);
    cudaFuncSetAttribute(gemm_fused<1024, 0>, cudaFuncAttributeMaxDynamicSharedMemorySize, SMEM_BYTES);
    cudaFuncSetAttribute(gemm_fused<2048, 0>, cudaFuncAttributeMaxDynamicSharedMemorySize, SMEM_BYTES);
    cudaFuncSetAttribute(gemm_fused<1024, 1>, cudaFuncAttributeMaxDynamicSharedMemorySize, SMEM_BYTES);

    const int T = 256;
    split_x_kernel<<<(N_B * IN_F / 4 + T - 1) / T, T>>>(x, xs);
    prep_w1_split<<<(3 * H1D * IN_F / 2 + T - 1) / T, T>>>(W1, G1, B1, M1, V1, w1p, c1);
    prep_we_split<<<(H2D * H1D / 2 + T - 1) / T, T>>>(W2, G2, B2, M2, V2, w2p, c2, H2D, H1D);
    prep_we_split<<<(H1D * H2D / 2 + T - 1) / T, T>>>(W3, G3, B3, M3, V3, w3p, c3, H1D, H2D);
    prep_we_split<<<(IN_F * H1D / 2 + T - 1) / T, T>>>(W4, G4, B4, M4, V4, w4p, c4, IN_F, H1D);

    // L1: [8192,512] x [3072,512]^T -> h1 [8192,3072]
    gemm_fused<512, 0><<<dim3(3 * H1D / 128, N_B / 128), T, SMEM_BYTES>>>(xs, w1p, c1, h1, N_B, 3 * H1D);
    gate1_split<<<(N_B * 128 + T - 1) / T, T>>>(h1, h1s);
    // L2: [24576,1024] x [2048,1024]^T
    gemm_fused<1024, 0><<<dim3(H2D / 128, 3 * N_B / 128), T, SMEM_BYTES>>>(h1s, w2p, c2, h2, 3 * N_B, H2D);
    gate_split<<<(int)((N_B * (size_t)H2D / 8 + T - 1) / T), T>>>(h2, h2s, (size_t)N_B * H2D);
    // L3: [24576,2048] x [1024,2048]^T
    gemm_fused<2048, 0><<<dim3(H1D / 128, 3 * N_B / 128), T, SMEM_BYTES>>>(h2s, w3p, c3, h3, 3 * N_B, H1D);
    gate_split<<<(int)((N_B * (size_t)H1D / 8 + T - 1) / T), T>>>(h3, h3s, (size_t)N_B * H1D);
    // L4: [24576,1024] x [512,1024]^T -> interleaved out [b][o][s]
    gemm_fused<1024, 1><<<dim3(IN_F / 128, 3 * N_B / 128), T, SMEM_BYTES>>>(h3s, w4p, c4, out, 3 * N_B, IN_F);
}